// round 9
// baseline (speedup 1.0000x reference)
#include <cuda_runtime.h>
#include <cstdint>

// ---------------------------------------------------------------------------
// MetaMLP (3-step GraphNet) on GB300 — edge GEMM with cp.async-pipelined,
// pre-swizzled bf16 hi/lo edge-feature storage; atomic aggregation.
// ---------------------------------------------------------------------------

#define D 128
static constexpr int N_NODES  = 50000;
static constexpr int N_EDGES  = 800000;
static constexpr int N_GRAPHS = 16;
static constexpr int OUTW     = 4 * D;            // 512 output cols per row
static constexpr int TILE_E   = 128;              // edges per tile
static constexpr int N_TILES  = N_EDGES / TILE_E; // 6250
static constexpr int TILE_BYTES = 65536;          // 32KB hi + 32KB lo

typedef unsigned long long u64;

// ------------------------- device scratch (no allocs) ----------------------
__device__ uint4 g_eaimg[(size_t)N_TILES * TILE_BYTES / 16];  // 409.6 MB
__device__ float g_P12 [(size_t)N_NODES  * 2 * D];   // [P1+uW4b+b | P2]
__device__ float g_agg [(size_t)N_NODES  * D];
__device__ float g_u    [N_GRAPHS * D];
__device__ float g_uWn3b[N_GRAPHS * D];
__device__ float g_gsum [N_GRAPHS * D];
__device__ float g_invN [N_NODES];
__device__ float g_invG [N_GRAPHS];

// ------------------------------ helpers ------------------------------------
__device__ __forceinline__ u64 pack2(float a, float b) {
    u64 r; asm("mov.b64 %0, {%1, %2};" : "=l"(r) : "f"(a), "f"(b)); return r;
}
__device__ __forceinline__ float2 unpack2(u64 v) {
    float2 r; asm("mov.b64 {%0, %1}, %2;" : "=f"(r.x), "=f"(r.y) : "l"(v)); return r;
}
__device__ __forceinline__ void ffma2(u64& d, u64 a, u64 b) {
    asm("fma.rn.f32x2 %0, %1, %2, %3;" : "=l"(d) : "l"(a), "l"(b), "l"(d));
}
__device__ __forceinline__ uint32_t cvt_bf16x2(float a, float b) {
    uint32_t r;
    asm("cvt.rn.bf16x2.f32 %0, %1, %2;" : "=r"(r) : "f"(b), "f"(a));
    return r;
}
__device__ __forceinline__ void split2(float x, float y, uint32_t& hi, uint32_t& lo) {
    hi = cvt_bf16x2(x, y);
    float hx = __uint_as_float(hi << 16);
    float hy = __uint_as_float(hi & 0xffff0000u);
    lo = cvt_bf16x2(x - hx, y - hy);
}
__device__ __forceinline__ void mma_bf16(float* d, const uint32_t* a, uint32_t b0, uint32_t b1) {
    asm volatile("mma.sync.aligned.m16n8k16.row.col.f32.bf16.bf16.f32 "
        "{%0,%1,%2,%3}, {%4,%5,%6,%7}, {%8,%9}, {%0,%1,%2,%3};"
        : "+f"(d[0]), "+f"(d[1]), "+f"(d[2]), "+f"(d[3])
        : "r"(a[0]), "r"(a[1]), "r"(a[2]), "r"(a[3]), "r"(b0), "r"(b1));
}
__device__ __forceinline__ void red_add2(float* addr, float x, float y) {
    asm volatile("red.global.add.v2.f32 [%0], {%1, %2};"
                 :: "l"(addr), "f"(x), "f"(y) : "memory");
}
__device__ __forceinline__ uint32_t smem_u32(const void* p) {
    uint32_t a;
    asm("{ .reg .u64 t; cvta.to.shared.u64 t, %1; cvt.u32.u64 %0, t; }" : "=r"(a) : "l"(p));
    return a;
}
__device__ __forceinline__ void ldsm_x4(uint32_t& r0, uint32_t& r1, uint32_t& r2, uint32_t& r3,
                                        uint32_t addr) {
    asm volatile("ldmatrix.sync.aligned.m8n8.x4.shared.b16 {%0,%1,%2,%3}, [%4];"
                 : "=r"(r0), "=r"(r1), "=r"(r2), "=r"(r3) : "r"(addr));
}
__device__ __forceinline__ void cp16(uint32_t saddr, const void* gaddr) {
    asm volatile("cp.async.cg.shared.global [%0], [%1], 16;" :: "r"(saddr), "l"(gaddr));
}

// ------------------------------ init (launch 0) -----------------------------
__global__ void init_kernel(const float* __restrict__ x, const float* __restrict__ u,
                            float* __restrict__ out_x, float* __restrict__ out_g) {
    int stride = gridDim.x * blockDim.x;
    int tid0 = blockIdx.x * blockDim.x + threadIdx.x;
    for (int i = tid0; i < N_NODES * D; i += stride) {
        int r = i >> 7, c = i & (D - 1);
        out_x[(size_t)r * OUTW + c] = x[i];
        g_agg[i] = 0.f;
    }
    for (int i = tid0; i < N_GRAPHS * D; i += stride) {
        int r = i >> 7, c = i & (D - 1);
        out_g[(size_t)r * OUTW + c] = u[i];
        g_u[i] = u[i];
    }
    for (int i = tid0; i < N_NODES; i += stride) g_invN[i] = 0.f;
    for (int i = tid0; i < N_GRAPHS; i += stride) g_invG[i] = 0.f;
}

// ------------------------------ hist / finalize ------------------------------
__global__ void hist_kernel(const int* __restrict__ dst, const int* __restrict__ batch) {
    int stride = gridDim.x * blockDim.x;
    int tid0 = blockIdx.x * blockDim.x + threadIdx.x;
    for (int i = tid0; i < N_EDGES; i += stride) atomicAdd(&g_invN[dst[i]], 1.f);
    for (int i = tid0; i < N_NODES; i += stride) atomicAdd(&g_invG[batch[i]], 1.f);
}

__global__ void finalize_counts_kernel() {
    int stride = gridDim.x * blockDim.x;
    int tid0 = blockIdx.x * blockDim.x + threadIdx.x;
    for (int i = tid0; i < N_NODES; i += stride) g_invN[i] = 1.f / fmaxf(g_invN[i], 1.f);
    for (int i = tid0; i < N_GRAPHS; i += stride) g_invG[i] = 1.f / fmaxf(g_invG[i], 1.f);
}

// ----------------------- matvec P1/P2 (512 thr, 16 warps) -------------------
__global__ void __launch_bounds__(512) matvec_P_kernel(
    const float* __restrict__ X, const float* __restrict__ W_edge,
    const float* __restrict__ b_edge, const int* __restrict__ batch) {
    extern __shared__ float sh[];
    float* sW1 = sh;
    float* sW2 = sh + 16384;
    float* sV  = sh + 32768;
    float* sGu = sh + 49152;
    float* sUW = sh + 51200;
    for (int i = threadIdx.x; i < D * D; i += blockDim.x) {
        sW1[i] = W_edge[i];
        sW2[i] = W_edge[D * D + i];
    }
    for (int i = threadIdx.x; i < N_GRAPHS * D; i += blockDim.x) sGu[i] = g_u[i];
    __syncthreads();
    {
        int j = threadIdx.x & 127, q4 = threadIdx.x >> 7;
        float acc[4];
#pragma unroll
        for (int q = 0; q < 4; q++) acc[q] = 0.f;
        const float* W4 = W_edge + 3 * D * D;
        for (int k = 0; k < D; k++) {
            float w = __ldg(W4 + k * D + j);
#pragma unroll
            for (int q = 0; q < 4; q++)
                acc[q] = fmaf(sGu[(q4 * 4 + q) * D + k], w, acc[q]);
        }
        float bj = __ldg(b_edge + j);
#pragma unroll
        for (int q = 0; q < 4; q++) sUW[(q4 * 4 + q) * D + j] = acc[q] + bj;
    }
    __syncthreads();
    int warp = threadIdx.x >> 5, lane = threadIdx.x & 31;
    float* myV = sV + warp * 8 * D;
    const int groups = N_NODES / 8;
    for (int grp = blockIdx.x * 16 + warp; grp < groups; grp += gridDim.x * 16) {
        int r0 = grp * 8;
#pragma unroll
        for (int e = 0; e < 8; e++) {
            float4 v = *((const float4*)(X + (size_t)(r0 + e) * OUTW) + lane);
            *((float4*)(myV + e * D) + lane) = v;
        }
        __syncwarp();
        u64 a0[8], a1[8], b0[8], b1[8];
#pragma unroll
        for (int e = 0; e < 8; e++) { a0[e] = a1[e] = b0[e] = b1[e] = 0ull; }
        for (int k = 0; k < D; k += 4) {
            ulonglong2 u0 = *((const ulonglong2*)(sW1 + (k + 0) * D) + lane);
            ulonglong2 u1 = *((const ulonglong2*)(sW1 + (k + 1) * D) + lane);
            ulonglong2 u2 = *((const ulonglong2*)(sW1 + (k + 2) * D) + lane);
            ulonglong2 u3 = *((const ulonglong2*)(sW1 + (k + 3) * D) + lane);
            ulonglong2 v0 = *((const ulonglong2*)(sW2 + (k + 0) * D) + lane);
            ulonglong2 v1 = *((const ulonglong2*)(sW2 + (k + 1) * D) + lane);
            ulonglong2 v2 = *((const ulonglong2*)(sW2 + (k + 2) * D) + lane);
            ulonglong2 v3 = *((const ulonglong2*)(sW2 + (k + 3) * D) + lane);
#pragma unroll
            for (int e = 0; e < 8; e++) {
                float4 a = *(const float4*)(myV + e * D + k);
                u64 p;
                p = pack2(a.x, a.x);
                ffma2(a0[e], p, u0.x); ffma2(a1[e], p, u0.y);
                ffma2(b0[e], p, v0.x); ffma2(b1[e], p, v0.y);
                p = pack2(a.y, a.y);
                ffma2(a0[e], p, u1.x); ffma2(a1[e], p, u1.y);
                ffma2(b0[e], p, v1.x); ffma2(b1[e], p, v1.y);
                p = pack2(a.z, a.z);
                ffma2(a0[e], p, u2.x); ffma2(a1[e], p, u2.y);
                ffma2(b0[e], p, v2.x); ffma2(b1[e], p, v2.y);
                p = pack2(a.w, a.w);
                ffma2(a0[e], p, u3.x); ffma2(a1[e], p, u3.y);
                ffma2(b0[e], p, v3.x); ffma2(b1[e], p, v3.y);
            }
        }
#pragma unroll
        for (int e = 0; e < 8; e++) {
            int g = __ldg(batch + r0 + e);
            float4 uv = *((const float4*)(sUW + g * D) + lane);
            float2 r01 = unpack2(a0[e]), r23 = unpack2(a1[e]);
            float2 s01 = unpack2(b0[e]), s23 = unpack2(b1[e]);
            float* base = g_P12 + (size_t)(r0 + e) * (2 * D);
            *((float4*)base + lane) =
                make_float4(r01.x + uv.x, r01.y + uv.y, r23.x + uv.z, r23.y + uv.w);
            *((float4*)(base + D) + lane) = make_float4(s01.x, s01.y, s23.x, s23.y);
        }
        __syncwarp();
    }
}

// ------------------------- edge kernel: mma.sync ----------------------------
// ea' = relu(ea@We3 + P1'[src] + P2[dst]); red-add to agg.
// ea stored as pre-swizzled bf16 hi/lo tile images -> cp.async pipelined.
__global__ void __launch_bounds__(512, 1) edge_mma_kernel(
    int step0, int store_ea, const float* __restrict__ ext_ea,
    const int* __restrict__ src, const int* __restrict__ dst,
    const float* __restrict__ We3) {
    extern __shared__ char smemraw[];
    uint4* sB  = (uint4*)smemraw;                 // 64 KB
    char*  bufs = smemraw + 65536;                // 2 x 64 KB (hi 32 + lo 32)

    int tid = threadIdx.x;
    for (int i = tid; i < 16 * 8 * 32; i += 512) {
        int lane = i & 31, ks = (i >> 5) & 7, nt = i >> 8;
        int gidw = lane >> 2, tigw = lane & 3;
        int n  = nt * 8 + gidw;
        int k0 = ks * 16 + tigw * 2;
        float w00 = __ldg(We3 + k0 * D + n);
        float w01 = __ldg(We3 + (k0 + 1) * D + n);
        float w10 = __ldg(We3 + (k0 + 8) * D + n);
        float w11 = __ldg(We3 + (k0 + 9) * D + n);
        uint32_t b0h, b0l, b1h, b1l;
        split2(w00, w01, b0h, b0l);
        split2(w10, w11, b1h, b1l);
        sB[i] = make_uint4(b0h, b1h, b0l, b1l);
    }

    int wid = tid >> 5, lane = tid & 31;
    int gid = lane >> 2, tig = lane & 3;
    int wm = wid & 3, wn = wid >> 2;
    __syncthreads();

    // prologue: async-stage first tile (steps 1,2)
    if (!step0 && (int)blockIdx.x < N_TILES) {
        const char* g = (const char*)g_eaimg + (size_t)blockIdx.x * TILE_BYTES;
        uint32_t sb = smem_u32(bufs);
#pragma unroll
        for (int q = 0; q < 8; q++) {
            int off = (tid + q * 512) * 16;
            cp16(sb + off, g + off);
        }
        asm volatile("cp.async.commit_group;");
    }

    int itc = 0;
    for (int tile = blockIdx.x; tile < N_TILES; tile += gridDim.x, itc++) {
        char* bufc = bufs + (itc & 1) * TILE_BYTES;
        char* bufn = bufs + ((itc & 1) ^ 1) * TILE_BYTES;
        uint32_t sc = smem_u32(bufc);

        if (step0) {
            // synchronous convert-stage from external f32
#pragma unroll
            for (int q = 0; q < 4; q++) {
                int u = tid + q * 512;          // 128 rows x 16 units
                int row = u >> 4, c16 = u & 15;
                const float* p = ext_ea + (size_t)(tile * TILE_E + row) * D + c16 * 8;
                float4 v0 = __ldcs((const float4*)p);
                float4 v1 = __ldcs((const float4*)(p + 4));
                uint32_t h0, l0, h1, l1, h2, l2, h3, l3;
                split2(v0.x, v0.y, h0, l0); split2(v0.z, v0.w, h1, l1);
                split2(v1.x, v1.y, h2, l2); split2(v1.z, v1.w, h3, l3);
                int sw = row * 256 + ((c16 ^ (row & 7)) << 4);
                *(uint4*)(bufc + sw)         = make_uint4(h0, h1, h2, h3);
                *(uint4*)(bufc + 32768 + sw) = make_uint4(l0, l1, l2, l3);
            }
        } else {
            int nx = tile + gridDim.x;
            if (nx < N_TILES) {
                const char* g = (const char*)g_eaimg + (size_t)nx * TILE_BYTES;
                uint32_t sn = smem_u32(bufn);
#pragma unroll
                for (int q = 0; q < 8; q++) {
                    int off = (tid + q * 512) * 16;
                    cp16(sn + off, g + off);
                }
            }
            asm volatile("cp.async.commit_group;");
            asm volatile("cp.async.wait_group %0;" :: "n"(1));
        }
        __syncthreads();

        // ---- MMA mainloop ----
        float acc[2][4][4];
#pragma unroll
        for (int mt = 0; mt < 2; mt++)
#pragma unroll
            for (int nt = 0; nt < 4; nt++)
#pragma unroll
                for (int q = 0; q < 4; q++) acc[mt][nt][q] = 0.f;

#pragma unroll
        for (int ks = 0; ks < 8; ks++) {
            uint32_t ah[2][4], al[2][4];
#pragma unroll
            for (int mt = 0; mt < 2; mt++) {
                int rowA = wm * 32 + mt * 16 + (lane & 15);
                int unit = ks * 2 + (lane >> 4);
                uint32_t off = rowA * 256 + (((unit ^ (rowA & 7)) & 15) << 4);
                ldsm_x4(ah[mt][0], ah[mt][1], ah[mt][2], ah[mt][3], sc + off);
                ldsm_x4(al[mt][0], al[mt][1], al[mt][2], al[mt][3], sc + 32768 + off);
            }
#pragma unroll
            for (int nt = 0; nt < 4; nt++) {
                uint4 b = sB[((wn * 4 + nt) * 8 + ks) * 32 + lane];
#pragma unroll
                for (int mt = 0; mt < 2; mt++) {
                    mma_bf16(acc[mt][nt], ah[mt], b.x, b.y);
                    mma_bf16(acc[mt][nt], ah[mt], b.z, b.w);
                    mma_bf16(acc[mt][nt], al[mt], b.x, b.y);
                }
            }
        }
        __syncthreads();

        // ---- dump acc to smem f32 (aliases bufc; MMA reads done) ----
#pragma unroll
        for (int mt = 0; mt < 2; mt++)
#pragma unroll
            for (int h = 0; h < 2; h++) {
                int row = wm * 32 + mt * 16 + h * 8 + gid;
#pragma unroll
                for (int nt = 0; nt < 4; nt++) {
                    int col = wn * 32 + nt * 8 + tig * 2;
                    int u = col >> 2;
                    uint32_t off = row * 512 + (((u ^ (row & 7)) & 31) << 4) + ((col << 2) & 15);
                    *(float2*)(bufc + off) =
                        make_float2(acc[mt][nt][h * 2], acc[mt][nt][h * 2 + 1]);
                }
            }
        __syncthreads();

        // ---- epilogue: 4 lanes/edge, write bf16 hi/lo image + reds ----
        {
            int rloc = tid >> 2, lc = tid & 3;
            int r = tile * TILE_E + rloc;
            int s = __ldg(src + r), d = __ldg(dst + r);
            const float4* p1b = (const float4*)(g_P12 + (size_t)s * 256);
            const float4* p2b = (const float4*)(g_P12 + (size_t)d * 256 + 128);
            char* hi_out = (char*)g_eaimg + (size_t)tile * TILE_BYTES + rloc * 256;
            char* lo_out = hi_out + 32768;
            float* ao = g_agg + (size_t)d * D;
            int rsw = rloc & 7;
#pragma unroll
            for (int w = lc * 4; w < lc * 4 + 4; w++) {
                int u0 = 2 * w, u1 = 2 * w + 1;
                float4 a0 = *(float4*)(bufc + rloc * 512 + (((u0 ^ rsw) & 31) << 4));
                float4 a1 = *(float4*)(bufc + rloc * 512 + (((u1 ^ rsw) & 31) << 4));
                float4 q0 = __ldg(p1b + u0), q1 = __ldg(p1b + u1);
                float4 t0 = __ldg(p2b + u0), t1 = __ldg(p2b + u1);
                float4 r0, r1;
                r0.x = fmaxf(a0.x + q0.x + t0.x, 0.f);
                r0.y = fmaxf(a0.y + q0.y + t0.y, 0.f);
                r0.z = fmaxf(a0.z + q0.z + t0.z, 0.f);
                r0.w = fmaxf(a0.w + q0.w + t0.w, 0.f);
                r1.x = fmaxf(a1.x + q1.x + t1.x, 0.f);
                r1.y = fmaxf(a1.y + q1.y + t1.y, 0.f);
                r1.z = fmaxf(a1.z + q1.z + t1.z, 0.f);
                r1.w = fmaxf(a1.w + q1.w + t1.w, 0.f);
                if (store_ea) {
                    uint32_t h0, l0, h1, l1, h2, l2, h3, l3;
                    split2(r0.x, r0.y, h0, l0); split2(r0.z, r0.w, h1, l1);
                    split2(r1.x, r1.y, h2, l2); split2(r1.z, r1.w, h3, l3);
                    int sw = (w ^ rsw) << 4;
                    *(uint4*)(hi_out + sw) = make_uint4(h0, h1, h2, h3);
                    *(uint4*)(lo_out + sw) = make_uint4(l0, l1, l2, l3);
                }
                red_add2(ao + u0 * 4,     r0.x, r0.y);
                red_add2(ao + u0 * 4 + 2, r0.z, r0.w);
                red_add2(ao + u1 * 4,     r1.x, r1.y);
                red_add2(ao + u1 * 4 + 2, r1.z, r1.w);
            }
        }
        __syncthreads();
    }
}

// --------------------------- prep2 (uWn3b + gsum=0) -------------------------
__global__ void prep2_kernel(const float* __restrict__ W_node,
                             const float* __restrict__ b_node) {
    int g = blockIdx.x, j = threadIdx.x;
    __shared__ float su[D];
    su[j] = g_u[g * D + j];
    __syncthreads();
    const float* W3 = W_node + 2 * D * D;
    float acc = b_node[j];
#pragma unroll 8
    for (int k = 0; k < D; k++) acc = fmaf(su[k], W3[k * D + j], acc);
    g_uWn3b[g * D + j] = acc;
    g_gsum[g * D + j] = 0.f;
}

// ------------------------- node kernel (512 thr, 16 warps) ------------------
__global__ void __launch_bounds__(512) node_kernel(
    const float* __restrict__ Xin, float* __restrict__ Xout,
    const int* __restrict__ batch, const float* __restrict__ W_node) {
    extern __shared__ float sh[];
    float* sW = sh;
    float* sU = sh + 2 * D * D;
    float* sV = sU + N_GRAPHS * D;
    for (int i = threadIdx.x; i < 2 * D * D; i += blockDim.x) sW[i] = W_node[i];
    for (int i = threadIdx.x; i < N_GRAPHS * D; i += blockDim.x) sU[i] = g_uWn3b[i];
    __syncthreads();
    int warp = threadIdx.x >> 5, lane = threadIdx.x & 31;
    float* myV = sV + warp * 4 * (2 * D);
    const int groups = N_NODES / 4;
    for (int grp = blockIdx.x * 16 + warp; grp < groups; grp += gridDim.x * 16) {
        int r0 = grp * 4;
#pragma unroll
        for (int e = 0; e < 4; e++) {
            int row = r0 + e;
            float4 xv = *((const float4*)(Xin + (size_t)row * OUTW) + lane);
            *((float4*)(myV + e * 2 * D) + lane) = xv;
            float inv = __ldg(&g_invN[row]);
            float4 av = *((const float4*)(g_agg + (size_t)row * D) + lane);
            *((float4*)(g_agg + (size_t)row * D) + lane) = make_float4(0.f, 0.f, 0.f, 0.f);
            av.x *= inv; av.y *= inv; av.z *= inv; av.w *= inv;
            *((float4*)(myV + e * 2 * D + D) + lane) = av;
        }
        __syncwarp();
        u64 acc0[4], acc1[4];
#pragma unroll
        for (int e = 0; e < 4; e++) { acc0[e] = 0ull; acc1[e] = 0ull; }
        for (int k = 0; k < 2 * D; k += 4) {
            ulonglong2 w0 = *((const ulonglong2*)(sW + (k + 0) * D) + lane);
            ulonglong2 w1 = *((const ulonglong2*)(sW + (k + 1) * D) + lane);
            ulonglong2 w2 = *((const ulonglong2*)(sW + (k + 2) * D) + lane);
            ulonglong2 w3 = *((const ulonglong2*)(sW + (k + 3) * D) + lane);
#pragma unroll
            for (int e = 0; e < 4; e++) {
                float4 a = *(const float4*)(myV + e * 2 * D + k);
                u64 p;
                p = pack2(a.x, a.x); ffma2(acc0[e], p, w0.x); ffma2(acc1[e], p, w0.y);
                p = pack2(a.y, a.y); ffma2(acc0[e], p, w1.x); ffma2(acc1[e], p, w1.y);
                p = pack2(a.z, a.z); ffma2(acc0[e], p, w2.x); ffma2(acc1[e], p, w2.y);
                p = pack2(a.w, a.w); ffma2(acc0[e], p, w3.x); ffma2(acc1[e], p, w3.y);
            }
        }
#pragma unroll
        for (int e = 0; e < 4; e++) {
            int row = r0 + e;
            int g = __ldg(batch + row);
            float4 ub = *((const float4*)(sU + g * D) + lane);
            float2 c01 = unpack2(acc0[e]), c23 = unpack2(acc1[e]);
            float4 r;
            r.x = fmaxf(c01.x + ub.x, 0.f);
            r.y = fmaxf(c01.y + ub.y, 0.f);
            r.z = fmaxf(c23.x + ub.z, 0.f);
            r.w = fmaxf(c23.y + ub.w, 0.f);
            *((float4*)(Xout + (size_t)row * OUTW) + lane) = r;
            atomicAdd((float4*)(g_gsum + g * D) + lane, r);
        }
        __syncwarp();
    }
}

// ------------------------------ global kernel ------------------------------
__global__ void global_kernel(const float* __restrict__ W_glob,
                              const float* __restrict__ b_glob,
                              float* __restrict__ out_g) {
    int g = blockIdx.x;
    int j = threadIdx.x;
    __shared__ float su[D], sm[D];
    su[j] = g_u[g * D + j];
    sm[j] = g_gsum[g * D + j] * g_invG[g];
    __syncthreads();
    float acc = b_glob[j];
#pragma unroll 4
    for (int k = 0; k < D; k++) acc = fmaf(su[k], W_glob[k * D + j], acc);
#pragma unroll 4
    for (int k = 0; k < D; k++) acc = fmaf(sm[k], W_glob[(D + k) * D + j], acc);
    float r = fmaxf(acc, 0.f);
    out_g[(size_t)g * OUTW + j] = r;
    g_u[g * D + j] = r;
}

// --------------------------------- launch ----------------------------------
extern "C" void kernel_launch(void* const* d_in, const int* in_sizes, int n_in,
                              void* d_out, int out_size) {
    const float* x      = (const float*)d_in[0];
    const int*   ei     = (const int*)d_in[1];
    const float* ea     = (const float*)d_in[2];
    const float* u      = (const float*)d_in[3];
    const int*   batch  = (const int*)d_in[4];
    const float* W_edge = (const float*)d_in[5];
    const float* b_edge = (const float*)d_in[6];
    const float* W_node = (const float*)d_in[7];
    const float* b_node = (const float*)d_in[8];
    const float* W_glob = (const float*)d_in[9];
    const float* b_glob = (const float*)d_in[10];

    const int* src = ei;
    const int* dstp = ei + N_EDGES;

    float* out   = (float*)d_out;
    float* out_x = out;                            // 50000 x 512
    float* out_g = out + (size_t)N_NODES * OUTW;   // 16 x 512

    const int MV_SMEM   = 53248 * 4;               // 208 KB
    const int EDGE_SMEM = 65536 + 2 * TILE_BYTES;  // 192 KB
    const int NODE_SMEM = (2 * D * D + N_GRAPHS * D + 16 * 4 * 2 * D) * 4;  // 200 KB

    cudaFuncSetAttribute(matvec_P_kernel, cudaFuncAttributeMaxDynamicSharedMemorySize, MV_SMEM);
    cudaFuncSetAttribute(edge_mma_kernel, cudaFuncAttributeMaxDynamicSharedMemorySize, EDGE_SMEM);
    cudaFuncSetAttribute(node_kernel,     cudaFuncAttributeMaxDynamicSharedMemorySize, NODE_SMEM);

    // launch order: index 3 (ncu capture point) = edge_mma_kernel
    init_kernel<<<2048, 256>>>(x, u, out_x, out_g);                        // 0
    matvec_P_kernel<<<148, 512, MV_SMEM>>>(out_x, W_edge, b_edge, batch);  // 1 (t=0)
    hist_kernel<<<1024, 256>>>(dstp, batch);                               // 2
    edge_mma_kernel<<<148, 512, EDGE_SMEM>>>(1, 1, ea, src, dstp,          // 3 PROFILED
                                             W_edge + 2 * D * D);
    finalize_counts_kernel<<<256, 256>>>();                                // 4

    for (int t = 0; t < 3; t++) {
        const float* Xt = out_x + t * D;
        float*       Xn = out_x + (t + 1) * D;

        prep2_kernel<<<16, 128>>>(W_node, b_node);
        node_kernel<<<148, 512, NODE_SMEM>>>(Xt, Xn, batch, W_node);
        global_kernel<<<16, 128>>>(W_glob, b_glob, out_g + (t + 1) * D);

        if (t < 2) {
            matvec_P_kernel<<<148, 512, MV_SMEM>>>(Xn, W_edge, b_edge, batch);
            edge_mma_kernel<<<148, 512, EDGE_SMEM>>>(0, (t + 1) < 2 ? 1 : 0, ea,
                                                     src, dstp, W_edge + 2 * D * D);
        }
    }
}

// round 10
// speedup vs baseline: 1.5010x; 1.5010x over previous
#include <cuda_runtime.h>
#include <cstdint>

// ---------------------------------------------------------------------------
// MetaMLP (3-step GraphNet) on GB300 — R7 edge (measured best) + mma.sync
// matvec/node kernels (same 3-product bf16-split machinery, light epilogues).
// ---------------------------------------------------------------------------

#define D 128
static constexpr int N_NODES  = 50000;
static constexpr int N_EDGES  = 800000;
static constexpr int N_GRAPHS = 16;
static constexpr int OUTW     = 4 * D;          // 512 output cols per row
static constexpr int N_TILES  = N_EDGES / 128;  // 6250
static constexpr int N_RTILES = (N_NODES + 127) / 128;  // 391

typedef unsigned long long u64;

// ------------------------- device scratch (no allocs) ----------------------
__device__ float g_ea  [(size_t)N_EDGES  * D];
__device__ float g_P12 [(size_t)N_NODES  * 2 * D];   // [P1+uW4b+b | P2]
__device__ float g_agg [(size_t)N_NODES  * D];
__device__ float g_u    [N_GRAPHS * D];
__device__ float g_uWn3b[N_GRAPHS * D];
__device__ float g_gsum [N_GRAPHS * D];
__device__ float g_invN [N_NODES];
__device__ float g_invG [N_GRAPHS];

// ------------------------------ helpers ------------------------------------
__device__ __forceinline__ uint32_t cvt_bf16x2(float a, float b) {
    uint32_t r;
    asm("cvt.rn.bf16x2.f32 %0, %1, %2;" : "=r"(r) : "f"(b), "f"(a));
    return r;
}
__device__ __forceinline__ void split2(float x, float y, uint32_t& hi, uint32_t& lo) {
    hi = cvt_bf16x2(x, y);
    float hx = __uint_as_float(hi << 16);
    float hy = __uint_as_float(hi & 0xffff0000u);
    lo = cvt_bf16x2(x - hx, y - hy);
}
__device__ __forceinline__ void mma_bf16(float* d, const uint32_t* a, uint32_t b0, uint32_t b1) {
    asm volatile("mma.sync.aligned.m16n8k16.row.col.f32.bf16.bf16.f32 "
        "{%0,%1,%2,%3}, {%4,%5,%6,%7}, {%8,%9}, {%0,%1,%2,%3};"
        : "+f"(d[0]), "+f"(d[1]), "+f"(d[2]), "+f"(d[3])
        : "r"(a[0]), "r"(a[1]), "r"(a[2]), "r"(a[3]), "r"(b0), "r"(b1));
}
__device__ __forceinline__ void red_add2(float* addr, float x, float y) {
    asm volatile("red.global.add.v2.f32 [%0], {%1, %2};"
                 :: "l"(addr), "f"(x), "f"(y) : "memory");
}

// ------------------------------ init (launch 0) -----------------------------
__global__ void init_kernel(const float* __restrict__ x, const float* __restrict__ u,
                            float* __restrict__ out_x, float* __restrict__ out_g) {
    int stride = gridDim.x * blockDim.x;
    int tid0 = blockIdx.x * blockDim.x + threadIdx.x;
    for (int i = tid0; i < N_NODES * D; i += stride) {
        int r = i >> 7, c = i & (D - 1);
        out_x[(size_t)r * OUTW + c] = x[i];
        g_agg[i] = 0.f;
    }
    for (int i = tid0; i < N_GRAPHS * D; i += stride) {
        int r = i >> 7, c = i & (D - 1);
        out_g[(size_t)r * OUTW + c] = u[i];
        g_u[i] = u[i];
    }
    for (int i = tid0; i < N_NODES; i += stride) g_invN[i] = 0.f;
    for (int i = tid0; i < N_GRAPHS; i += stride) g_invG[i] = 0.f;
}

// ------------------------------ hist / finalize ------------------------------
__global__ void hist_kernel(const int* __restrict__ dst, const int* __restrict__ batch) {
    int stride = gridDim.x * blockDim.x;
    int tid0 = blockIdx.x * blockDim.x + threadIdx.x;
    for (int i = tid0; i < N_EDGES; i += stride) atomicAdd(&g_invN[dst[i]], 1.f);
    for (int i = tid0; i < N_NODES; i += stride) atomicAdd(&g_invG[batch[i]], 1.f);
}

__global__ void finalize_counts_kernel() {
    int stride = gridDim.x * blockDim.x;
    int tid0 = blockIdx.x * blockDim.x + threadIdx.x;
    for (int i = tid0; i < N_NODES; i += stride) g_invN[i] = 1.f / fmaxf(g_invN[i], 1.f);
    for (int i = tid0; i < N_GRAPHS; i += stride) g_invG[i] = 1.f / fmaxf(g_invG[i], 1.f);
}

__global__ void zero_agg_kernel() {
    int stride = gridDim.x * blockDim.x;
    for (int i = blockIdx.x * blockDim.x + threadIdx.x; i < N_NODES * D / 4; i += stride)
        ((float4*)g_agg)[i] = make_float4(0.f, 0.f, 0.f, 0.f);
}

// ----------------------- matvec P1/P2 (mma.sync, 512 thr) -------------------
// g_P12[row] = [ X@We1 + (u@We4+b_edge)[batch[row]] | X@We2 ]
__global__ void __launch_bounds__(512, 1) matvec_mma_kernel(
    const float* __restrict__ Xin, const float* __restrict__ W_edge,
    const float* __restrict__ b_edge, const int* __restrict__ batch) {
    extern __shared__ char smemraw[];
    uint4* sB  = (uint4*)smemraw;                 // [nt32][ks8][lane32] 128 KB
    float* sGu = (float*)(smemraw + 131072);      // 8 KB
    float* sUW = (float*)(smemraw + 139264);      // 8 KB
    int tid = threadIdx.x;

    for (int i = tid; i < 32 * 8 * 32; i += 512) {
        int lane = i & 31, ks = (i >> 5) & 7, nt = i >> 8;
        int gidw = lane >> 2, tigw = lane & 3;
        int n  = nt * 8 + gidw;                   // 0..255 (W1 | W2)
        int k0 = ks * 16 + tigw * 2;
        const float* W = (n < D) ? (W_edge + n) : (W_edge + D * D + (n - D));
        float w00 = __ldg(W + k0 * D);
        float w01 = __ldg(W + (k0 + 1) * D);
        float w10 = __ldg(W + (k0 + 8) * D);
        float w11 = __ldg(W + (k0 + 9) * D);
        uint32_t b0h, b0l, b1h, b1l;
        split2(w00, w01, b0h, b0l);
        split2(w10, w11, b1h, b1l);
        sB[i] = make_uint4(b0h, b1h, b0l, b1l);
    }
    for (int i = tid; i < N_GRAPHS * D; i += 512) sGu[i] = g_u[i];
    __syncthreads();
    // in-block uW4b (+ bias)
    {
        int j = tid & 127, q4 = tid >> 7;
        float acc[4];
#pragma unroll
        for (int q = 0; q < 4; q++) acc[q] = 0.f;
        const float* W4 = W_edge + 3 * D * D;
        for (int k = 0; k < D; k++) {
            float w = __ldg(W4 + k * D + j);
#pragma unroll
            for (int q = 0; q < 4; q++)
                acc[q] = fmaf(sGu[(q4 * 4 + q) * D + k], w, acc[q]);
        }
        float bj = __ldg(b_edge + j);
#pragma unroll
        for (int q = 0; q < 4; q++) sUW[(q4 * 4 + q) * D + j] = acc[q] + bj;
    }
    __syncthreads();

    int wid = tid >> 5, lane = tid & 31;
    int gid = lane >> 2, tig = lane & 3;
    int wm = wid & 3, wn = wid >> 2;    // 4 m-slices x 4 n-quarters(64 cols)

    for (int tile = blockIdx.x; tile < N_RTILES; tile += gridDim.x) {
        int rbase = tile * 128 + wm * 32;
        float acc[2][8][4];
#pragma unroll
        for (int mt = 0; mt < 2; mt++)
#pragma unroll
            for (int nt = 0; nt < 8; nt++)
#pragma unroll
                for (int q = 0; q < 4; q++) acc[mt][nt][q] = 0.f;

        const float* pA[2];
#pragma unroll
        for (int mt = 0; mt < 2; mt++) {
            int r0 = rbase + mt * 16 + gid;
            if (r0 > N_NODES - 1) r0 = N_NODES - 1;          // clamp (loads only)
            pA[mt] = Xin + (size_t)r0 * OUTW + tig * 2;
        }
        // row+8 clamp handled by separate pointer
        const float* pA8[2];
#pragma unroll
        for (int mt = 0; mt < 2; mt++) {
            int r1 = rbase + mt * 16 + 8 + gid;
            if (r1 > N_NODES - 1) r1 = N_NODES - 1;
            pA8[mt] = Xin + (size_t)r1 * OUTW + tig * 2;
        }

#pragma unroll
        for (int ks = 0; ks < 8; ks++) {
            uint32_t ah[2][4], al[2][4];
#pragma unroll
            for (int mt = 0; mt < 2; mt++) {
                float2 v0 = __ldg((const float2*)(pA[mt]  + ks * 16));
                float2 v1 = __ldg((const float2*)(pA8[mt] + ks * 16));
                float2 v2 = __ldg((const float2*)(pA[mt]  + ks * 16 + 8));
                float2 v3 = __ldg((const float2*)(pA8[mt] + ks * 16 + 8));
                split2(v0.x, v0.y, ah[mt][0], al[mt][0]);
                split2(v1.x, v1.y, ah[mt][1], al[mt][1]);
                split2(v2.x, v2.y, ah[mt][2], al[mt][2]);
                split2(v3.x, v3.y, ah[mt][3], al[mt][3]);
            }
#pragma unroll
            for (int nt = 0; nt < 8; nt++) {
                uint4 b = sB[((wn * 8 + nt) * 8 + ks) * 32 + lane];
#pragma unroll
                for (int mt = 0; mt < 2; mt++) {
                    mma_bf16(acc[mt][nt], ah[mt], b.x, b.y);
                    mma_bf16(acc[mt][nt], ah[mt], b.z, b.w);
                    mma_bf16(acc[mt][nt], al[mt], b.x, b.y);
                }
            }
        }

        // epilogue: rows -> g_P12 (stride 256); P1 half adds uW4b
#pragma unroll
        for (int mt = 0; mt < 2; mt++) {
#pragma unroll
            for (int h = 0; h < 2; h++) {
                int row = rbase + mt * 16 + h * 8 + gid;
                if (row < N_NODES) {
                    int g = __ldg(batch + row);
                    float* base = g_P12 + (size_t)row * 256;
#pragma unroll
                    for (int nt = 0; nt < 8; nt++) {
                        int n = wn * 64 + nt * 8 + tig * 2;   // 0..255
                        float vx = acc[mt][nt][h * 2 + 0];
                        float vy = acc[mt][nt][h * 2 + 1];
                        if (n < D) {
                            float2 uv = *(float2*)(sUW + g * D + n);
                            vx += uv.x; vy += uv.y;
                        }
                        *(float2*)(base + n) = make_float2(vx, vy);
                    }
                }
            }
        }
    }
}

// ------------------------- edge kernel (R7 verbatim) ------------------------
__global__ void __launch_bounds__(256, 2) edge_mma_kernel(
    int step0, int store_ea, const float* __restrict__ ext_ea,
    const int* __restrict__ src, const int* __restrict__ dst,
    const float* __restrict__ We3) {
    extern __shared__ uint4 sBe[];   // [nt=16][ks=8][lane=32]
    int tid = threadIdx.x;

    for (int i = tid; i < 16 * 8 * 32; i += 256) {
        int lane = i & 31, ks = (i >> 5) & 7, nt = i >> 8;
        int gidw = lane >> 2, tigw = lane & 3;
        int n  = nt * 8 + gidw;
        int k0 = ks * 16 + tigw * 2;
        float w00 = __ldg(We3 + k0 * D + n);
        float w01 = __ldg(We3 + (k0 + 1) * D + n);
        float w10 = __ldg(We3 + (k0 + 8) * D + n);
        float w11 = __ldg(We3 + (k0 + 9) * D + n);
        uint32_t b0h, b0l, b1h, b1l;
        split2(w00, w01, b0h, b0l);
        split2(w10, w11, b1h, b1l);
        sBe[i] = make_uint4(b0h, b1h, b0l, b1l);
    }
    __syncthreads();

    int wid = tid >> 5, lane = tid & 31;
    int gid = lane >> 2, tig = lane & 3;
    int wm = wid & 3, wn = wid >> 2;
    const float* ea_in = step0 ? ext_ea : (const float*)g_ea;

    for (int tile = blockIdx.x; tile < N_TILES; tile += gridDim.x) {
        const float* A = ea_in + (size_t)tile * (128 * 128);
        const float* base0 = A + (wm * 32 + 0 * 16 + gid) * 128 + tig * 2;
        const float* base1 = A + (wm * 32 + 1 * 16 + gid) * 128 + tig * 2;

        int sidx[2][2], didx[2][2];
#pragma unroll
        for (int mt = 0; mt < 2; mt++)
#pragma unroll
            for (int h = 0; h < 2; h++) {
                int r = tile * 128 + wm * 32 + mt * 16 + h * 8 + gid;
                sidx[mt][h] = __ldg(src + r);
                didx[mt][h] = __ldg(dst + r);
            }

        float acc[2][8][4];
#pragma unroll
        for (int mt = 0; mt < 2; mt++)
#pragma unroll
            for (int nt = 0; nt < 8; nt++)
#pragma unroll
                for (int q = 0; q < 4; q++) acc[mt][nt][q] = 0.f;

        float2 cur[2][4], nxt[2][4];
#pragma unroll
        for (int mt = 0; mt < 2; mt++) {
            const float* b = mt ? base1 : base0;
            cur[mt][0] = __ldg((const float2*)b);
            cur[mt][1] = __ldg((const float2*)(b + 8 * 128));
            cur[mt][2] = __ldg((const float2*)(b + 8));
            cur[mt][3] = __ldg((const float2*)(b + 8 * 128 + 8));
        }
#pragma unroll
        for (int ks = 0; ks < 8; ks++) {
            if (ks < 7) {
#pragma unroll
                for (int mt = 0; mt < 2; mt++) {
                    const float* b = (mt ? base1 : base0) + (ks + 1) * 16;
                    nxt[mt][0] = __ldg((const float2*)b);
                    nxt[mt][1] = __ldg((const float2*)(b + 8 * 128));
                    nxt[mt][2] = __ldg((const float2*)(b + 8));
                    nxt[mt][3] = __ldg((const float2*)(b + 8 * 128 + 8));
                }
            }
            uint32_t ah[2][4], al[2][4];
#pragma unroll
            for (int mt = 0; mt < 2; mt++)
#pragma unroll
                for (int q = 0; q < 4; q++)
                    split2(cur[mt][q].x, cur[mt][q].y, ah[mt][q], al[mt][q]);
#pragma unroll
            for (int nt = 0; nt < 8; nt++) {
                uint4 b = sBe[((wn * 8 + nt) * 8 + ks) * 32 + lane];
#pragma unroll
                for (int mt = 0; mt < 2; mt++) {
                    mma_bf16(acc[mt][nt], ah[mt], b.x, b.y);
                    mma_bf16(acc[mt][nt], ah[mt], b.z, b.w);
                    mma_bf16(acc[mt][nt], al[mt], b.x, b.y);
                }
            }
#pragma unroll
            for (int mt = 0; mt < 2; mt++)
#pragma unroll
                for (int q = 0; q < 4; q++) cur[mt][q] = nxt[mt][q];
        }

#pragma unroll
        for (int mt = 0; mt < 2; mt++) {
#pragma unroll
            for (int h = 0; h < 2; h++) {
                int r = tile * 128 + wm * 32 + mt * 16 + h * 8 + gid;
                int s = sidx[mt][h], d = didx[mt][h];
                const float* p1b = g_P12 + (size_t)s * 256;
                const float* p2b = g_P12 + (size_t)d * 256 + 128;
                float* eo = g_ea + (size_t)r * D;
                float* ao = g_agg + (size_t)d * D;
#pragma unroll
                for (int nt = 0; nt < 8; nt++) {
                    int c = wn * 64 + nt * 8 + tig * 2;
                    float2 p1 = __ldg((const float2*)(p1b + c));
                    float2 p2 = __ldg((const float2*)(p2b + c));
                    float rx = fmaxf(acc[mt][nt][h * 2 + 0] + p1.x + p2.x, 0.f);
                    float ry = fmaxf(acc[mt][nt][h * 2 + 1] + p1.y + p2.y, 0.f);
                    if (store_ea) *(float2*)(eo + c) = make_float2(rx, ry);
                    red_add2(ao + c, rx, ry);
                }
            }
        }
    }
}

// --------------------------- prep2 (uWn3b + gsum=0) -------------------------
__global__ void prep2_kernel(const float* __restrict__ W_node,
                             const float* __restrict__ b_node) {
    int g = blockIdx.x, j = threadIdx.x;
    __shared__ float su[D];
    su[j] = g_u[g * D + j];
    __syncthreads();
    const float* W3 = W_node + 2 * D * D;
    float acc = b_node[j];
#pragma unroll 8
    for (int k = 0; k < D; k++) acc = fmaf(su[k], W3[k * D + j], acc);
    g_uWn3b[g * D + j] = acc;
    g_gsum[g * D + j] = 0.f;
}

// ------------------------- node kernel (mma.sync, 512 thr) ------------------
// x' = relu([x, agg/deg] @ Wn12 + uWn3b[batch]); per-graph sums via reds.
__global__ void __launch_bounds__(512, 1) node_mma_kernel(
    const float* __restrict__ Xin, float* __restrict__ Xout,
    const int* __restrict__ batch, const float* __restrict__ W_node) {
    extern __shared__ char smemraw[];
    uint4* sB = (uint4*)smemraw;                  // [nt16][ks16][lane32] 128 KB
    float* sU = (float*)(smemraw + 131072);       // 8 KB
    int tid = threadIdx.x;

    for (int i = tid; i < 16 * 16 * 32; i += 512) {
        int lane = i & 31, ks = (i >> 5) & 15, nt = i >> 9;
        int gidw = lane >> 2, tigw = lane & 3;
        int n  = nt * 8 + gidw;                   // 0..127
        int k0 = ks * 16 + tigw * 2;              // 0..255
        float w00 = __ldg(W_node + k0 * D + n);
        float w01 = __ldg(W_node + (k0 + 1) * D + n);
        float w10 = __ldg(W_node + (k0 + 8) * D + n);
        float w11 = __ldg(W_node + (k0 + 9) * D + n);
        uint32_t b0h, b0l, b1h, b1l;
        split2(w00, w01, b0h, b0l);
        split2(w10, w11, b1h, b1l);
        sB[i] = make_uint4(b0h, b1h, b0l, b1l);
    }
    for (int i = tid; i < N_GRAPHS * D; i += 512) sU[i] = g_uWn3b[i];
    __syncthreads();

    int wid = tid >> 5, lane = tid & 31;
    int gid = lane >> 2, tig = lane & 3;
    int wm = wid & 3, wn = wid >> 2;   // 4 m-slices x 4 n-quarters(32 cols)

    for (int tile = blockIdx.x; tile < N_RTILES; tile += gridDim.x) {
        int rbase = tile * 128 + wm * 32;
        int r0c[2], r1c[2];
        float inv0[2], inv1[2];
#pragma unroll
        for (int mt = 0; mt < 2; mt++) {
            int r0 = rbase + mt * 16 + gid;      if (r0 > N_NODES - 1) r0 = N_NODES - 1;
            int r1 = rbase + mt * 16 + 8 + gid;  if (r1 > N_NODES - 1) r1 = N_NODES - 1;
            r0c[mt] = r0; r1c[mt] = r1;
            inv0[mt] = __ldg(&g_invN[r0]);
            inv1[mt] = __ldg(&g_invN[r1]);
        }

        float acc[2][4][4];
#pragma unroll
        for (int mt = 0; mt < 2; mt++)
#pragma unroll
            for (int nt = 0; nt < 4; nt++)
#pragma unroll
                for (int q = 0; q < 4; q++) acc[mt][nt][q] = 0.f;

#pragma unroll
        for (int ks = 0; ks < 16; ks++) {
            uint32_t ah[2][4], al[2][4];
#pragma unroll
            for (int mt = 0; mt < 2; mt++) {
                float2 v0, v1, v2, v3;
                if (ks < 8) {
                    const float* p0 = Xin + (size_t)r0c[mt] * OUTW + ks * 16 + tig * 2;
                    const float* p1 = Xin + (size_t)r1c[mt] * OUTW + ks * 16 + tig * 2;
                    v0 = __ldg((const float2*)p0);
                    v1 = __ldg((const float2*)p1);
                    v2 = __ldg((const float2*)(p0 + 8));
                    v3 = __ldg((const float2*)(p1 + 8));
                } else {
                    const float* p0 = g_agg + (size_t)r0c[mt] * D + (ks - 8) * 16 + tig * 2;
                    const float* p1 = g_agg + (size_t)r1c[mt] * D + (ks - 8) * 16 + tig * 2;
                    v0 = __ldg((const float2*)p0);
                    v1 = __ldg((const float2*)p1);
                    v2 = __ldg((const float2*)(p0 + 8));
                    v3 = __ldg((const float2*)(p1 + 8));
                    v0.x *= inv0[mt]; v0.y *= inv0[mt];
                    v1.x *= inv1[mt]; v1.y *= inv1[mt];
                    v2.x *= inv0[mt]; v2.y *= inv0[mt];
                    v3.x *= inv1[mt]; v3.y *= inv1[mt];
                }
                split2(v0.x, v0.y, ah[mt][0], al[mt][0]);
                split2(v1.x, v1.y, ah[mt][1], al[mt][1]);
                split2(v2.x, v2.y, ah[mt][2], al[mt][2]);
                split2(v3.x, v3.y, ah[mt][3], al[mt][3]);
            }
#pragma unroll
            for (int nt = 0; nt < 4; nt++) {
                uint4 b = sB[((wn * 4 + nt) * 16 + ks) * 32 + lane];
#pragma unroll
                for (int mt = 0; mt < 2; mt++) {
                    mma_bf16(acc[mt][nt], ah[mt], b.x, b.y);
                    mma_bf16(acc[mt][nt], ah[mt], b.z, b.w);
                    mma_bf16(acc[mt][nt], al[mt], b.x, b.y);
                }
            }
        }

        // epilogue: relu, store Xout rows, red per-graph sums
#pragma unroll
        for (int mt = 0; mt < 2; mt++) {
#pragma unroll
            for (int h = 0; h < 2; h++) {
                int row = rbase + mt * 16 + h * 8 + gid;
                if (row < N_NODES) {
                    int g = __ldg(batch + row);
                    float* xo = Xout + (size_t)row * OUTW;
#pragma unroll
                    for (int nt = 0; nt < 4; nt++) {
                        int c = wn * 32 + nt * 8 + tig * 2;
                        float2 uv = *(float2*)(sU + g * D + c);
                        float rx = fmaxf(acc[mt][nt][h * 2 + 0] + uv.x, 0.f);
                        float ry = fmaxf(acc[mt][nt][h * 2 + 1] + uv.y, 0.f);
                        *(float2*)(xo + c) = make_float2(rx, ry);
                        red_add2(g_gsum + g * D + c, rx, ry);
                    }
                }
            }
        }
    }
}

// ------------------------------ global kernel ------------------------------
__global__ void global_kernel(const float* __restrict__ W_glob,
                              const float* __restrict__ b_glob,
                              float* __restrict__ out_g) {
    int g = blockIdx.x;
    int j = threadIdx.x;
    __shared__ float su[D], sm[D];
    su[j] = g_u[g * D + j];
    sm[j] = g_gsum[g * D + j] * g_invG[g];
    __syncthreads();
    float acc = b_glob[j];
#pragma unroll 4
    for (int k = 0; k < D; k++) acc = fmaf(su[k], W_glob[k * D + j], acc);
#pragma unroll 4
    for (int k = 0; k < D; k++) acc = fmaf(sm[k], W_glob[(D + k) * D + j], acc);
    float r = fmaxf(acc, 0.f);
    out_g[(size_t)g * OUTW + j] = r;
    g_u[g * D + j] = r;
}

// --------------------------------- launch ----------------------------------
extern "C" void kernel_launch(void* const* d_in, const int* in_sizes, int n_in,
                              void* d_out, int out_size) {
    const float* x      = (const float*)d_in[0];
    const int*   ei     = (const int*)d_in[1];
    const float* ea     = (const float*)d_in[2];
    const float* u      = (const float*)d_in[3];
    const int*   batch  = (const int*)d_in[4];
    const float* W_edge = (const float*)d_in[5];
    const float* b_edge = (const float*)d_in[6];
    const float* W_node = (const float*)d_in[7];
    const float* b_node = (const float*)d_in[8];
    const float* W_glob = (const float*)d_in[9];
    const float* b_glob = (const float*)d_in[10];

    const int* src = ei;
    const int* dstp = ei + N_EDGES;

    float* out   = (float*)d_out;
    float* out_x = out;                            // 50000 x 512
    float* out_g = out + (size_t)N_NODES * OUTW;   // 16 x 512

    const int MV_SMEM   = 131072 + 8192 + 8192;    // 147456
    const int EDGE_SMEM = 16 * 8 * 32 * 16;        // 64 KB
    const int NODE_SMEM = 131072 + 8192;           // 139264

    cudaFuncSetAttribute(matvec_mma_kernel, cudaFuncAttributeMaxDynamicSharedMemorySize, MV_SMEM);
    cudaFuncSetAttribute(edge_mma_kernel,   cudaFuncAttributeMaxDynamicSharedMemorySize, EDGE_SMEM);
    cudaFuncSetAttribute(node_mma_kernel,   cudaFuncAttributeMaxDynamicSharedMemorySize, NODE_SMEM);

    // launch order: index 3 (ncu capture point) = edge_mma_kernel
    init_kernel<<<2048, 256>>>(x, u, out_x, out_g);                          // 0
    matvec_mma_kernel<<<148, 512, MV_SMEM>>>(out_x, W_edge, b_edge, batch);  // 1 (t=0)
    hist_kernel<<<1024, 256>>>(dstp, batch);                                 // 2
    edge_mma_kernel<<<296, 256, EDGE_SMEM>>>(1, 1, ea, src, dstp,            // 3 PROFILED
                                             W_edge + 2 * D * D);
    finalize_counts_kernel<<<256, 256>>>();                                  // 4

    for (int t = 0; t < 3; t++) {
        const float* Xt = out_x + t * D;
        float*       Xn = out_x + (t + 1) * D;

        prep2_kernel<<<16, 128>>>(W_node, b_node);
        node_mma_kernel<<<148, 512, NODE_SMEM>>>(Xt, Xn, batch, W_node);
        zero_agg_kernel<<<1024, 256>>>();
        global_kernel<<<16, 128>>>(W_glob, b_glob, out_g + (t + 1) * D);

        if (t < 2) {
            matvec_mma_kernel<<<148, 512, MV_SMEM>>>(Xn, W_edge, b_edge, batch);
            edge_mma_kernel<<<296, 256, EDGE_SMEM>>>(0, (t + 1) < 2 ? 1 : 0, ea,
                                                     src, dstp, W_edge + 2 * D * D);
        }
    }
}

// round 11
// speedup vs baseline: 1.7165x; 1.1436x over previous
#include <cuda_runtime.h>
#include <cstdint>

// ---------------------------------------------------------------------------
// MetaMLP (3-step GraphNet) on GB300 — mma.sync everywhere; tig-pair float4
// epilogues (halved L1 wavefronts) + red.v4 aggregation.
// ---------------------------------------------------------------------------

#define D 128
static constexpr int N_NODES  = 50000;
static constexpr int N_EDGES  = 800000;
static constexpr int N_GRAPHS = 16;
static constexpr int OUTW     = 4 * D;          // 512 output cols per row
static constexpr int N_TILES  = N_EDGES / 128;  // 6250
static constexpr int N_RTILES = (N_NODES + 127) / 128;  // 391

typedef unsigned long long u64;

// ------------------------- device scratch (no allocs) ----------------------
__device__ float g_ea  [(size_t)N_EDGES  * D];
__device__ float g_P12 [(size_t)N_NODES  * 2 * D];   // [P1+uW4b+b | P2]
__device__ float g_agg [(size_t)N_NODES  * D];
__device__ float g_u    [N_GRAPHS * D];
__device__ float g_uWn3b[N_GRAPHS * D];
__device__ float g_gsum [N_GRAPHS * D];
__device__ float g_invN [N_NODES];
__device__ float g_invG [N_GRAPHS];

// ------------------------------ helpers ------------------------------------
__device__ __forceinline__ uint32_t cvt_bf16x2(float a, float b) {
    uint32_t r;
    asm("cvt.rn.bf16x2.f32 %0, %1, %2;" : "=r"(r) : "f"(b), "f"(a));
    return r;
}
__device__ __forceinline__ void split2(float x, float y, uint32_t& hi, uint32_t& lo) {
    hi = cvt_bf16x2(x, y);
    float hx = __uint_as_float(hi << 16);
    float hy = __uint_as_float(hi & 0xffff0000u);
    lo = cvt_bf16x2(x - hx, y - hy);
}
__device__ __forceinline__ void mma_bf16(float* d, const uint32_t* a, uint32_t b0, uint32_t b1) {
    asm volatile("mma.sync.aligned.m16n8k16.row.col.f32.bf16.bf16.f32 "
        "{%0,%1,%2,%3}, {%4,%5,%6,%7}, {%8,%9}, {%0,%1,%2,%3};"
        : "+f"(d[0]), "+f"(d[1]), "+f"(d[2]), "+f"(d[3])
        : "r"(a[0]), "r"(a[1]), "r"(a[2]), "r"(a[3]), "r"(b0), "r"(b1));
}
__device__ __forceinline__ void red_add4(float* addr, float4 v) {
    asm volatile("red.global.add.v4.f32 [%0], {%1, %2, %3, %4};"
                 :: "l"(addr), "f"(v.x), "f"(v.y), "f"(v.z), "f"(v.w) : "memory");
}

// tig-pair combine: even tig returns nt0's float4, odd tig returns nt1's.
// acc pairs: (a0,a1)=acc[nt0] cols tig*2,+1 ; (b0,b1)=acc[nt1].
__device__ __forceinline__ float4 pair_combine(float a0, float a1, float b0, float b1,
                                               bool even) {
    float sa0 = __shfl_xor_sync(0xffffffffu, a0, 1);
    float sa1 = __shfl_xor_sync(0xffffffffu, a1, 1);
    float sb0 = __shfl_xor_sync(0xffffffffu, b0, 1);
    float sb1 = __shfl_xor_sync(0xffffffffu, b1, 1);
    return even ? make_float4(a0, a1, sa0, sa1) : make_float4(sb0, sb1, b0, b1);
}

// ------------------------------ init (launch 0) -----------------------------
__global__ void init_kernel(const float* __restrict__ x, const float* __restrict__ u,
                            float* __restrict__ out_x, float* __restrict__ out_g) {
    int stride = gridDim.x * blockDim.x;
    int tid0 = blockIdx.x * blockDim.x + threadIdx.x;
    for (int i = tid0; i < N_NODES * D; i += stride) {
        int r = i >> 7, c = i & (D - 1);
        out_x[(size_t)r * OUTW + c] = x[i];
        g_agg[i] = 0.f;
    }
    for (int i = tid0; i < N_GRAPHS * D; i += stride) {
        int r = i >> 7, c = i & (D - 1);
        out_g[(size_t)r * OUTW + c] = u[i];
        g_u[i] = u[i];
    }
    for (int i = tid0; i < N_NODES; i += stride) g_invN[i] = 0.f;
    for (int i = tid0; i < N_GRAPHS; i += stride) g_invG[i] = 0.f;
}

// ------------------------------ hist / finalize ------------------------------
__global__ void hist_kernel(const int* __restrict__ dst, const int* __restrict__ batch) {
    int stride = gridDim.x * blockDim.x;
    int tid0 = blockIdx.x * blockDim.x + threadIdx.x;
    for (int i = tid0; i < N_EDGES; i += stride) atomicAdd(&g_invN[dst[i]], 1.f);
    for (int i = tid0; i < N_NODES; i += stride) atomicAdd(&g_invG[batch[i]], 1.f);
}

__global__ void finalize_counts_kernel() {
    int stride = gridDim.x * blockDim.x;
    int tid0 = blockIdx.x * blockDim.x + threadIdx.x;
    for (int i = tid0; i < N_NODES; i += stride) g_invN[i] = 1.f / fmaxf(g_invN[i], 1.f);
    for (int i = tid0; i < N_GRAPHS; i += stride) g_invG[i] = 1.f / fmaxf(g_invG[i], 1.f);
}

__global__ void zero_agg_kernel() {
    int stride = gridDim.x * blockDim.x;
    for (int i = blockIdx.x * blockDim.x + threadIdx.x; i < N_NODES * D / 4; i += stride)
        ((float4*)g_agg)[i] = make_float4(0.f, 0.f, 0.f, 0.f);
}

// ----------------------- matvec P1/P2 (mma.sync, 512 thr) -------------------
__global__ void __launch_bounds__(512, 1) matvec_mma_kernel(
    const float* __restrict__ Xin, const float* __restrict__ W_edge,
    const float* __restrict__ b_edge, const int* __restrict__ batch) {
    extern __shared__ char smemraw[];
    uint4* sB  = (uint4*)smemraw;                 // [nt32][ks8][lane32] 128 KB
    float* sGu = (float*)(smemraw + 131072);      // 8 KB
    float* sUW = (float*)(smemraw + 139264);      // 8 KB
    int tid = threadIdx.x;

    for (int i = tid; i < 32 * 8 * 32; i += 512) {
        int lane = i & 31, ks = (i >> 5) & 7, nt = i >> 8;
        int gidw = lane >> 2, tigw = lane & 3;
        int n  = nt * 8 + gidw;
        int k0 = ks * 16 + tigw * 2;
        const float* W = (n < D) ? (W_edge + n) : (W_edge + D * D + (n - D));
        float w00 = __ldg(W + k0 * D);
        float w01 = __ldg(W + (k0 + 1) * D);
        float w10 = __ldg(W + (k0 + 8) * D);
        float w11 = __ldg(W + (k0 + 9) * D);
        uint32_t b0h, b0l, b1h, b1l;
        split2(w00, w01, b0h, b0l);
        split2(w10, w11, b1h, b1l);
        sB[i] = make_uint4(b0h, b1h, b0l, b1l);
    }
    for (int i = tid; i < N_GRAPHS * D; i += 512) sGu[i] = g_u[i];
    __syncthreads();
    {
        int j = tid & 127, q4 = tid >> 7;
        float acc[4];
#pragma unroll
        for (int q = 0; q < 4; q++) acc[q] = 0.f;
        const float* W4 = W_edge + 3 * D * D;
        for (int k = 0; k < D; k++) {
            float w = __ldg(W4 + k * D + j);
#pragma unroll
            for (int q = 0; q < 4; q++)
                acc[q] = fmaf(sGu[(q4 * 4 + q) * D + k], w, acc[q]);
        }
        float bj = __ldg(b_edge + j);
#pragma unroll
        for (int q = 0; q < 4; q++) sUW[(q4 * 4 + q) * D + j] = acc[q] + bj;
    }
    __syncthreads();

    int wid = tid >> 5, lane = tid & 31;
    int gid = lane >> 2, tig = lane & 3;
    int wm = wid & 3, wn = wid >> 2;
    bool even = ((tig & 1) == 0);

    for (int tile = blockIdx.x; tile < N_RTILES; tile += gridDim.x) {
        int rbase = tile * 128 + wm * 32;
        float acc[2][8][4];
#pragma unroll
        for (int mt = 0; mt < 2; mt++)
#pragma unroll
            for (int nt = 0; nt < 8; nt++)
#pragma unroll
                for (int q = 0; q < 4; q++) acc[mt][nt][q] = 0.f;

        const float* pA[2];
        const float* pA8[2];
#pragma unroll
        for (int mt = 0; mt < 2; mt++) {
            int r0 = rbase + mt * 16 + gid;
            if (r0 > N_NODES - 1) r0 = N_NODES - 1;
            pA[mt] = Xin + (size_t)r0 * OUTW + tig * 2;
            int r1 = rbase + mt * 16 + 8 + gid;
            if (r1 > N_NODES - 1) r1 = N_NODES - 1;
            pA8[mt] = Xin + (size_t)r1 * OUTW + tig * 2;
        }

#pragma unroll
        for (int ks = 0; ks < 8; ks++) {
            uint32_t ah[2][4], al[2][4];
#pragma unroll
            for (int mt = 0; mt < 2; mt++) {
                float2 v0 = __ldg((const float2*)(pA[mt]  + ks * 16));
                float2 v1 = __ldg((const float2*)(pA8[mt] + ks * 16));
                float2 v2 = __ldg((const float2*)(pA[mt]  + ks * 16 + 8));
                float2 v3 = __ldg((const float2*)(pA8[mt] + ks * 16 + 8));
                split2(v0.x, v0.y, ah[mt][0], al[mt][0]);
                split2(v1.x, v1.y, ah[mt][1], al[mt][1]);
                split2(v2.x, v2.y, ah[mt][2], al[mt][2]);
                split2(v3.x, v3.y, ah[mt][3], al[mt][3]);
            }
#pragma unroll
            for (int nt = 0; nt < 8; nt++) {
                uint4 b = sB[((wn * 8 + nt) * 8 + ks) * 32 + lane];
#pragma unroll
                for (int mt = 0; mt < 2; mt++) {
                    mma_bf16(acc[mt][nt], ah[mt], b.x, b.y);
                    mma_bf16(acc[mt][nt], ah[mt], b.z, b.w);
                    mma_bf16(acc[mt][nt], al[mt], b.x, b.y);
                }
            }
        }

        // epilogue: tig-pair float4 stores to g_P12 (stride 256)
#pragma unroll
        for (int mt = 0; mt < 2; mt++) {
#pragma unroll
            for (int h = 0; h < 2; h++) {
                int row = rbase + mt * 16 + h * 8 + gid;
                bool ok = row < N_NODES;
                int g = __ldg(batch + (ok ? row : N_NODES - 1));
                float* base = g_P12 + (size_t)row * 256;
#pragma unroll
                for (int np = 0; np < 4; np++) {
                    int nt0 = 2 * np, nt1 = 2 * np + 1;
                    float4 v = pair_combine(acc[mt][nt0][h * 2], acc[mt][nt0][h * 2 + 1],
                                            acc[mt][nt1][h * 2], acc[mt][nt1][h * 2 + 1],
                                            even);
                    int n = wn * 64 + (even ? nt0 : nt1) * 8 + (tig & 2) * 2;
                    if (ok) {
                        if (n < D) {
                            float4 uv = *(float4*)(sUW + g * D + n);
                            v.x += uv.x; v.y += uv.y; v.z += uv.z; v.w += uv.w;
                        }
                        *(float4*)(base + n) = v;
                    }
                }
            }
        }
    }
}

// ------------------------- edge kernel: mma.sync ----------------------------
// ea' = relu(ea@We3 + P1'[src] + P2[dst]); red.v4 to agg; tig-pair epilogue.
__global__ void __launch_bounds__(256, 2) edge_mma_kernel(
    int step0, int store_ea, const float* __restrict__ ext_ea,
    const int* __restrict__ src, const int* __restrict__ dst,
    const float* __restrict__ We3) {
    extern __shared__ uint4 sBe[];   // [nt=16][ks=8][lane=32]
    int tid = threadIdx.x;

    for (int i = tid; i < 16 * 8 * 32; i += 256) {
        int lane = i & 31, ks = (i >> 5) & 7, nt = i >> 8;
        int gidw = lane >> 2, tigw = lane & 3;
        int n  = nt * 8 + gidw;
        int k0 = ks * 16 + tigw * 2;
        float w00 = __ldg(We3 + k0 * D + n);
        float w01 = __ldg(We3 + (k0 + 1) * D + n);
        float w10 = __ldg(We3 + (k0 + 8) * D + n);
        float w11 = __ldg(We3 + (k0 + 9) * D + n);
        uint32_t b0h, b0l, b1h, b1l;
        split2(w00, w01, b0h, b0l);
        split2(w10, w11, b1h, b1l);
        sBe[i] = make_uint4(b0h, b1h, b0l, b1l);
    }
    __syncthreads();

    int wid = tid >> 5, lane = tid & 31;
    int gid = lane >> 2, tig = lane & 3;
    int wm = wid & 3, wn = wid >> 2;
    bool even = ((tig & 1) == 0);
    const float* ea_in = step0 ? ext_ea : (const float*)g_ea;

    for (int tile = blockIdx.x; tile < N_TILES; tile += gridDim.x) {
        const float* A = ea_in + (size_t)tile * (128 * 128);
        const float* base0 = A + (wm * 32 + 0 * 16 + gid) * 128 + tig * 2;
        const float* base1 = A + (wm * 32 + 1 * 16 + gid) * 128 + tig * 2;

        int sidx[2][2], didx[2][2];
#pragma unroll
        for (int mt = 0; mt < 2; mt++)
#pragma unroll
            for (int h = 0; h < 2; h++) {
                int r = tile * 128 + wm * 32 + mt * 16 + h * 8 + gid;
                sidx[mt][h] = __ldg(src + r);
                didx[mt][h] = __ldg(dst + r);
            }

        float acc[2][8][4];
#pragma unroll
        for (int mt = 0; mt < 2; mt++)
#pragma unroll
            for (int nt = 0; nt < 8; nt++)
#pragma unroll
                for (int q = 0; q < 4; q++) acc[mt][nt][q] = 0.f;

        float2 cur[2][4], nxt[2][4];
#pragma unroll
        for (int mt = 0; mt < 2; mt++) {
            const float* b = mt ? base1 : base0;
            cur[mt][0] = __ldg((const float2*)b);
            cur[mt][1] = __ldg((const float2*)(b + 8 * 128));
            cur[mt][2] = __ldg((const float2*)(b + 8));
            cur[mt][3] = __ldg((const float2*)(b + 8 * 128 + 8));
        }
#pragma unroll
        for (int ks = 0; ks < 8; ks++) {
            if (ks < 7) {
#pragma unroll
                for (int mt = 0; mt < 2; mt++) {
                    const float* b = (mt ? base1 : base0) + (ks + 1) * 16;
                    nxt[mt][0] = __ldg((const float2*)b);
                    nxt[mt][1] = __ldg((const float2*)(b + 8 * 128));
                    nxt[mt][2] = __ldg((const float2*)(b + 8));
                    nxt[mt][3] = __ldg((const float2*)(b + 8 * 128 + 8));
                }
            }
            uint32_t ah[2][4], al[2][4];
#pragma unroll
            for (int mt = 0; mt < 2; mt++)
#pragma unroll
                for (int q = 0; q < 4; q++)
                    split2(cur[mt][q].x, cur[mt][q].y, ah[mt][q], al[mt][q]);
#pragma unroll
            for (int nt = 0; nt < 8; nt++) {
                uint4 b = sBe[((wn * 8 + nt) * 8 + ks) * 32 + lane];
#pragma unroll
                for (int mt = 0; mt < 2; mt++) {
                    mma_bf16(acc[mt][nt], ah[mt], b.x, b.y);
                    mma_bf16(acc[mt][nt], ah[mt], b.z, b.w);
                    mma_bf16(acc[mt][nt], al[mt], b.x, b.y);
                }
            }
#pragma unroll
            for (int mt = 0; mt < 2; mt++)
#pragma unroll
                for (int q = 0; q < 4; q++) cur[mt][q] = nxt[mt][q];
        }

        // tig-pair float4 epilogue
#pragma unroll
        for (int mt = 0; mt < 2; mt++) {
#pragma unroll
            for (int h = 0; h < 2; h++) {
                int r = tile * 128 + wm * 32 + mt * 16 + h * 8 + gid;
                int s = sidx[mt][h], d = didx[mt][h];
                const float* p1b = g_P12 + (size_t)s * 256;
                const float* p2b = g_P12 + (size_t)d * 256 + 128;
                float* eo = g_ea + (size_t)r * D;
                float* ao = g_agg + (size_t)d * D;
#pragma unroll
                for (int np = 0; np < 4; np++) {
                    int nt0 = 2 * np, nt1 = 2 * np + 1;
                    float4 v = pair_combine(acc[mt][nt0][h * 2], acc[mt][nt0][h * 2 + 1],
                                            acc[mt][nt1][h * 2], acc[mt][nt1][h * 2 + 1],
                                            even);
                    int c = wn * 64 + (even ? nt0 : nt1) * 8 + (tig & 2) * 2;
                    float4 p1 = __ldg((const float4*)(p1b + c));
                    float4 p2 = __ldg((const float4*)(p2b + c));
                    float4 rr;
                    rr.x = fmaxf(v.x + p1.x + p2.x, 0.f);
                    rr.y = fmaxf(v.y + p1.y + p2.y, 0.f);
                    rr.z = fmaxf(v.z + p1.z + p2.z, 0.f);
                    rr.w = fmaxf(v.w + p1.w + p2.w, 0.f);
                    if (store_ea) *(float4*)(eo + c) = rr;
                    red_add4(ao + c, rr);
                }
            }
        }
    }
}

// --------------------------- prep2 (uWn3b + gsum=0) -------------------------
__global__ void prep2_kernel(const float* __restrict__ W_node,
                             const float* __restrict__ b_node) {
    int g = blockIdx.x, j = threadIdx.x;
    __shared__ float su[D];
    su[j] = g_u[g * D + j];
    __syncthreads();
    const float* W3 = W_node + 2 * D * D;
    float acc = b_node[j];
#pragma unroll 8
    for (int k = 0; k < D; k++) acc = fmaf(su[k], W3[k * D + j], acc);
    g_uWn3b[g * D + j] = acc;
    g_gsum[g * D + j] = 0.f;
}

// ------------------------- node kernel (mma.sync, 512 thr) ------------------
__global__ void __launch_bounds__(512, 1) node_mma_kernel(
    const float* __restrict__ Xin, float* __restrict__ Xout,
    const int* __restrict__ batch, const float* __restrict__ W_node) {
    extern __shared__ char smemraw[];
    uint4* sB = (uint4*)smemraw;                  // [nt16][ks16][lane32] 128 KB
    float* sU = (float*)(smemraw + 131072);       // 8 KB
    int tid = threadIdx.x;

    for (int i = tid; i < 16 * 16 * 32; i += 512) {
        int lane = i & 31, ks = (i >> 5) & 15, nt = i >> 9;
        int gidw = lane >> 2, tigw = lane & 3;
        int n  = nt * 8 + gidw;
        int k0 = ks * 16 + tigw * 2;
        float w00 = __ldg(W_node + k0 * D + n);
        float w01 = __ldg(W_node + (k0 + 1) * D + n);
        float w10 = __ldg(W_node + (k0 + 8) * D + n);
        float w11 = __ldg(W_node + (k0 + 9) * D + n);
        uint32_t b0h, b0l, b1h, b1l;
        split2(w00, w01, b0h, b0l);
        split2(w10, w11, b1h, b1l);
        sB[i] = make_uint4(b0h, b1h, b0l, b1l);
    }
    for (int i = tid; i < N_GRAPHS * D; i += 512) sU[i] = g_uWn3b[i];
    __syncthreads();

    int wid = tid >> 5, lane = tid & 31;
    int gid = lane >> 2, tig = lane & 3;
    int wm = wid & 3, wn = wid >> 2;
    bool even = ((tig & 1) == 0);

    for (int tile = blockIdx.x; tile < N_RTILES; tile += gridDim.x) {
        int rbase = tile * 128 + wm * 32;
        int r0c[2], r1c[2];
        float inv0[2], inv1[2];
#pragma unroll
        for (int mt = 0; mt < 2; mt++) {
            int r0 = rbase + mt * 16 + gid;      if (r0 > N_NODES - 1) r0 = N_NODES - 1;
            int r1 = rbase + mt * 16 + 8 + gid;  if (r1 > N_NODES - 1) r1 = N_NODES - 1;
            r0c[mt] = r0; r1c[mt] = r1;
            inv0[mt] = __ldg(&g_invN[r0]);
            inv1[mt] = __ldg(&g_invN[r1]);
        }

        float acc[2][4][4];
#pragma unroll
        for (int mt = 0; mt < 2; mt++)
#pragma unroll
            for (int nt = 0; nt < 4; nt++)
#pragma unroll
                for (int q = 0; q < 4; q++) acc[mt][nt][q] = 0.f;

#pragma unroll
        for (int ks = 0; ks < 16; ks++) {
            uint32_t ah[2][4], al[2][4];
#pragma unroll
            for (int mt = 0; mt < 2; mt++) {
                float2 v0, v1, v2, v3;
                if (ks < 8) {
                    const float* p0 = Xin + (size_t)r0c[mt] * OUTW + ks * 16 + tig * 2;
                    const float* p1 = Xin + (size_t)r1c[mt] * OUTW + ks * 16 + tig * 2;
                    v0 = __ldg((const float2*)p0);
                    v1 = __ldg((const float2*)p1);
                    v2 = __ldg((const float2*)(p0 + 8));
                    v3 = __ldg((const float2*)(p1 + 8));
                } else {
                    const float* p0 = g_agg + (size_t)r0c[mt] * D + (ks - 8) * 16 + tig * 2;
                    const float* p1 = g_agg + (size_t)r1c[mt] * D + (ks - 8) * 16 + tig * 2;
                    v0 = __ldg((const float2*)p0);
                    v1 = __ldg((const float2*)p1);
                    v2 = __ldg((const float2*)(p0 + 8));
                    v3 = __ldg((const float2*)(p1 + 8));
                    v0.x *= inv0[mt]; v0.y *= inv0[mt];
                    v1.x *= inv1[mt]; v1.y *= inv1[mt];
                    v2.x *= inv0[mt]; v2.y *= inv0[mt];
                    v3.x *= inv1[mt]; v3.y *= inv1[mt];
                }
                split2(v0.x, v0.y, ah[mt][0], al[mt][0]);
                split2(v1.x, v1.y, ah[mt][1], al[mt][1]);
                split2(v2.x, v2.y, ah[mt][2], al[mt][2]);
                split2(v3.x, v3.y, ah[mt][3], al[mt][3]);
            }
#pragma unroll
            for (int nt = 0; nt < 4; nt++) {
                uint4 b = sB[((wn * 4 + nt) * 16 + ks) * 32 + lane];
#pragma unroll
                for (int mt = 0; mt < 2; mt++) {
                    mma_bf16(acc[mt][nt], ah[mt], b.x, b.y);
                    mma_bf16(acc[mt][nt], ah[mt], b.z, b.w);
                    mma_bf16(acc[mt][nt], al[mt], b.x, b.y);
                }
            }
        }

        // tig-pair float4 epilogue: Xout rows + red.v4 per-graph sums
#pragma unroll
        for (int mt = 0; mt < 2; mt++) {
#pragma unroll
            for (int h = 0; h < 2; h++) {
                int row = rbase + mt * 16 + h * 8 + gid;
                bool ok = row < N_NODES;
                int g = __ldg(batch + (ok ? row : N_NODES - 1));
                float* xo = Xout + (size_t)row * OUTW;
#pragma unroll
                for (int np = 0; np < 2; np++) {
                    int nt0 = 2 * np, nt1 = 2 * np + 1;
                    float4 v = pair_combine(acc[mt][nt0][h * 2], acc[mt][nt0][h * 2 + 1],
                                            acc[mt][nt1][h * 2], acc[mt][nt1][h * 2 + 1],
                                            even);
                    int c = wn * 32 + (even ? nt0 : nt1) * 8 + (tig & 2) * 2;
                    if (ok) {
                        float4 uv = *(float4*)(sU + g * D + c);
                        float4 rr;
                        rr.x = fmaxf(v.x + uv.x, 0.f);
                        rr.y = fmaxf(v.y + uv.y, 0.f);
                        rr.z = fmaxf(v.z + uv.z, 0.f);
                        rr.w = fmaxf(v.w + uv.w, 0.f);
                        *(float4*)(xo + c) = rr;
                        red_add4(g_gsum + g * D + c, rr);
                    }
                }
            }
        }
    }
}

// ------------------------------ global kernel ------------------------------
__global__ void global_kernel(const float* __restrict__ W_glob,
                              const float* __restrict__ b_glob,
                              float* __restrict__ out_g) {
    int g = blockIdx.x;
    int j = threadIdx.x;
    __shared__ float su[D], sm[D];
    su[j] = g_u[g * D + j];
    sm[j] = g_gsum[g * D + j] * g_invG[g];
    __syncthreads();
    float acc = b_glob[j];
#pragma unroll 4
    for (int k = 0; k < D; k++) acc = fmaf(su[k], W_glob[k * D + j], acc);
#pragma unroll 4
    for (int k = 0; k < D; k++) acc = fmaf(sm[k], W_glob[(D + k) * D + j], acc);
    float r = fmaxf(acc, 0.f);
    out_g[(size_t)g * OUTW + j] = r;
    g_u[g * D + j] = r;
}

// --------------------------------- launch ----------------------------------
extern "C" void kernel_launch(void* const* d_in, const int* in_sizes, int n_in,
                              void* d_out, int out_size) {
    const float* x      = (const float*)d_in[0];
    const int*   ei     = (const int*)d_in[1];
    const float* ea     = (const float*)d_in[2];
    const float* u      = (const float*)d_in[3];
    const int*   batch  = (const int*)d_in[4];
    const float* W_edge = (const float*)d_in[5];
    const float* b_edge = (const float*)d_in[6];
    const float* W_node = (const float*)d_in[7];
    const float* b_node = (const float*)d_in[8];
    const float* W_glob = (const float*)d_in[9];
    const float* b_glob = (const float*)d_in[10];

    const int* src = ei;
    const int* dstp = ei + N_EDGES;

    float* out   = (float*)d_out;
    float* out_x = out;                            // 50000 x 512
    float* out_g = out + (size_t)N_NODES * OUTW;   // 16 x 512

    const int MV_SMEM   = 131072 + 8192 + 8192;    // 147456
    const int EDGE_SMEM = 16 * 8 * 32 * 16;        // 64 KB
    const int NODE_SMEM = 131072 + 8192;           // 139264

    cudaFuncSetAttribute(matvec_mma_kernel, cudaFuncAttributeMaxDynamicSharedMemorySize, MV_SMEM);
    cudaFuncSetAttribute(edge_mma_kernel,   cudaFuncAttributeMaxDynamicSharedMemorySize, EDGE_SMEM);
    cudaFuncSetAttribute(node_mma_kernel,   cudaFuncAttributeMaxDynamicSharedMemorySize, NODE_SMEM);

    // launch order: index 3 (ncu capture point) = edge_mma_kernel
    init_kernel<<<2048, 256>>>(x, u, out_x, out_g);                          // 0
    matvec_mma_kernel<<<148, 512, MV_SMEM>>>(out_x, W_edge, b_edge, batch);  // 1 (t=0)
    hist_kernel<<<1024, 256>>>(dstp, batch);                                 // 2
    edge_mma_kernel<<<296, 256, EDGE_SMEM>>>(1, 1, ea, src, dstp,            // 3 PROFILED
                                             W_edge + 2 * D * D);
    finalize_counts_kernel<<<256, 256>>>();                                  // 4

    for (int t = 0; t < 3; t++) {
        const float* Xt = out_x + t * D;
        float*       Xn = out_x + (t + 1) * D;

        prep2_kernel<<<16, 128>>>(W_node, b_node);
        node_mma_kernel<<<148, 512, NODE_SMEM>>>(Xt, Xn, batch, W_node);
        zero_agg_kernel<<<1024, 256>>>();
        global_kernel<<<16, 128>>>(W_glob, b_glob, out_g + (t + 1) * D);

        if (t < 2) {
            matvec_mma_kernel<<<148, 512, MV_SMEM>>>(Xn, W_edge, b_edge, batch);
            edge_mma_kernel<<<296, 256, EDGE_SMEM>>>(0, (t + 1) < 2 ? 1 : 0, ea,
                                                     src, dstp, W_edge + 2 * D * D);
        }
    }
}

// round 12
// speedup vs baseline: 1.7751x; 1.0341x over previous
#include <cuda_runtime.h>
#include <cstdint>

// ---------------------------------------------------------------------------
// MetaMLP (3-step GraphNet) on GB300 — mma.sync everywhere; tig-pair float4
// epilogues; edge A-path widened to LDG.128 + xor-1 lane exchange; agg/gsum
// zeroing folded into node/global epilogues.
// ---------------------------------------------------------------------------

#define D 128
static constexpr int N_NODES  = 50000;
static constexpr int N_EDGES  = 800000;
static constexpr int N_GRAPHS = 16;
static constexpr int OUTW     = 4 * D;          // 512 output cols per row
static constexpr int N_TILES  = N_EDGES / 128;  // 6250
static constexpr int N_RTILES = (N_NODES + 127) / 128;  // 391

typedef unsigned long long u64;

// ------------------------- device scratch (no allocs) ----------------------
__device__ float g_ea  [(size_t)N_EDGES  * D];
__device__ float g_P12 [(size_t)N_NODES  * 2 * D];   // [P1+uW4b+b | P2]
__device__ float g_agg [(size_t)N_NODES  * D];
__device__ float g_u    [N_GRAPHS * D];
__device__ float g_uWn3b[N_GRAPHS * D];
__device__ float g_gsum [N_GRAPHS * D];
__device__ float g_invN [N_NODES];
__device__ float g_invG [N_GRAPHS];

// ------------------------------ helpers ------------------------------------
__device__ __forceinline__ uint32_t cvt_bf16x2(float a, float b) {
    uint32_t r;
    asm("cvt.rn.bf16x2.f32 %0, %1, %2;" : "=r"(r) : "f"(b), "f"(a));
    return r;
}
__device__ __forceinline__ void split2(float x, float y, uint32_t& hi, uint32_t& lo) {
    hi = cvt_bf16x2(x, y);
    float hx = __uint_as_float(hi << 16);
    float hy = __uint_as_float(hi & 0xffff0000u);
    lo = cvt_bf16x2(x - hx, y - hy);
}
__device__ __forceinline__ void mma_bf16(float* d, const uint32_t* a, uint32_t b0, uint32_t b1) {
    asm volatile("mma.sync.aligned.m16n8k16.row.col.f32.bf16.bf16.f32 "
        "{%0,%1,%2,%3}, {%4,%5,%6,%7}, {%8,%9}, {%0,%1,%2,%3};"
        : "+f"(d[0]), "+f"(d[1]), "+f"(d[2]), "+f"(d[3])
        : "r"(a[0]), "r"(a[1]), "r"(a[2]), "r"(a[3]), "r"(b0), "r"(b1));
}
__device__ __forceinline__ void red_add4(float* addr, float4 v) {
    asm volatile("red.global.add.v4.f32 [%0], {%1, %2, %3, %4};"
                 :: "l"(addr), "f"(v.x), "f"(v.y), "f"(v.z), "f"(v.w) : "memory");
}

// tig-pair combine: even tig returns nt0's float4, odd tig returns nt1's.
__device__ __forceinline__ float4 pair_combine(float a0, float a1, float b0, float b1,
                                               bool even) {
    float sa0 = __shfl_xor_sync(0xffffffffu, a0, 1);
    float sa1 = __shfl_xor_sync(0xffffffffu, a1, 1);
    float sb0 = __shfl_xor_sync(0xffffffffu, b0, 1);
    float sb1 = __shfl_xor_sync(0xffffffffu, b1, 1);
    return even ? make_float4(a0, a1, sa0, sa1) : make_float4(sb0, sb1, b0, b1);
}

// widened A-fragment build: lane loaded float4 at col (tig&1)*8+(tig>>1)*4.
// f covers 4 consecutive cols; xor-1 exchange of packed bf16 pairs completes
// the m16n8k16 fragment halves (even lanes own k-lo, odd lanes own k-hi).
__device__ __forceinline__ void frag_from_f4(float4 f, bool even,
                                             uint32_t& rlo_h, uint32_t& rlo_l,
                                             uint32_t& rhi_h, uint32_t& rhi_l) {
    uint32_t h01, l01, h23, l23;
    split2(f.x, f.y, h01, l01);
    split2(f.z, f.w, h23, l23);
    uint32_t sh01 = __shfl_xor_sync(0xffffffffu, h01, 1);
    uint32_t sl01 = __shfl_xor_sync(0xffffffffu, l01, 1);
    uint32_t sh23 = __shfl_xor_sync(0xffffffffu, h23, 1);
    uint32_t sl23 = __shfl_xor_sync(0xffffffffu, l23, 1);
    rlo_h = even ? h01 : sh23;   // reg (k-lo) hi
    rlo_l = even ? l01 : sl23;
    rhi_h = even ? sh01 : h23;   // reg (k-hi) hi
    rhi_l = even ? sl01 : l23;
}

// ------------------------------ init (launch 0) -----------------------------
__global__ void init_kernel(const float* __restrict__ x, const float* __restrict__ u,
                            float* __restrict__ out_x, float* __restrict__ out_g) {
    int stride = gridDim.x * blockDim.x;
    int tid0 = blockIdx.x * blockDim.x + threadIdx.x;
    for (int i = tid0; i < N_NODES * D; i += stride) {
        int r = i >> 7, c = i & (D - 1);
        out_x[(size_t)r * OUTW + c] = x[i];
        g_agg[i] = 0.f;
    }
    for (int i = tid0; i < N_GRAPHS * D; i += stride) {
        int r = i >> 7, c = i & (D - 1);
        out_g[(size_t)r * OUTW + c] = u[i];
        g_u[i] = u[i];
    }
    for (int i = tid0; i < N_NODES; i += stride) g_invN[i] = 0.f;
    for (int i = tid0; i < N_GRAPHS; i += stride) g_invG[i] = 0.f;
}

// ------------------------------ hist / finalize ------------------------------
__global__ void hist_kernel(const int* __restrict__ dst, const int* __restrict__ batch) {
    int stride = gridDim.x * blockDim.x;
    int tid0 = blockIdx.x * blockDim.x + threadIdx.x;
    for (int i = tid0; i < N_EDGES; i += stride) atomicAdd(&g_invN[dst[i]], 1.f);
    for (int i = tid0; i < N_NODES; i += stride) atomicAdd(&g_invG[batch[i]], 1.f);
}

__global__ void finalize_counts_kernel() {
    int stride = gridDim.x * blockDim.x;
    int tid0 = blockIdx.x * blockDim.x + threadIdx.x;
    for (int i = tid0; i < N_NODES; i += stride) g_invN[i] = 1.f / fmaxf(g_invN[i], 1.f);
    for (int i = tid0; i < N_GRAPHS; i += stride) g_invG[i] = 1.f / fmaxf(g_invG[i], 1.f);
}

// ----------------------- matvec P1/P2 (mma.sync, 512 thr) -------------------
__global__ void __launch_bounds__(512, 1) matvec_mma_kernel(
    const float* __restrict__ Xin, const float* __restrict__ W_edge,
    const float* __restrict__ b_edge, const int* __restrict__ batch) {
    extern __shared__ char smemraw[];
    uint4* sB  = (uint4*)smemraw;                 // [nt32][ks8][lane32] 128 KB
    float* sGu = (float*)(smemraw + 131072);      // 8 KB
    float* sUW = (float*)(smemraw + 139264);      // 8 KB
    int tid = threadIdx.x;

    for (int i = tid; i < 32 * 8 * 32; i += 512) {
        int lane = i & 31, ks = (i >> 5) & 7, nt = i >> 8;
        int gidw = lane >> 2, tigw = lane & 3;
        int n  = nt * 8 + gidw;
        int k0 = ks * 16 + tigw * 2;
        const float* W = (n < D) ? (W_edge + n) : (W_edge + D * D + (n - D));
        float w00 = __ldg(W + k0 * D);
        float w01 = __ldg(W + (k0 + 1) * D);
        float w10 = __ldg(W + (k0 + 8) * D);
        float w11 = __ldg(W + (k0 + 9) * D);
        uint32_t b0h, b0l, b1h, b1l;
        split2(w00, w01, b0h, b0l);
        split2(w10, w11, b1h, b1l);
        sB[i] = make_uint4(b0h, b1h, b0l, b1l);
    }
    for (int i = tid; i < N_GRAPHS * D; i += 512) sGu[i] = g_u[i];
    __syncthreads();
    {
        int j = tid & 127, q4 = tid >> 7;
        float acc[4];
#pragma unroll
        for (int q = 0; q < 4; q++) acc[q] = 0.f;
        const float* W4 = W_edge + 3 * D * D;
        for (int k = 0; k < D; k++) {
            float w = __ldg(W4 + k * D + j);
#pragma unroll
            for (int q = 0; q < 4; q++)
                acc[q] = fmaf(sGu[(q4 * 4 + q) * D + k], w, acc[q]);
        }
        float bj = __ldg(b_edge + j);
#pragma unroll
        for (int q = 0; q < 4; q++) sUW[(q4 * 4 + q) * D + j] = acc[q] + bj;
    }
    __syncthreads();

    int wid = tid >> 5, lane = tid & 31;
    int gid = lane >> 2, tig = lane & 3;
    int wm = wid & 3, wn = wid >> 2;
    bool even = ((tig & 1) == 0);

    for (int tile = blockIdx.x; tile < N_RTILES; tile += gridDim.x) {
        int rbase = tile * 128 + wm * 32;
        float acc[2][8][4];
#pragma unroll
        for (int mt = 0; mt < 2; mt++)
#pragma unroll
            for (int nt = 0; nt < 8; nt++)
#pragma unroll
                for (int q = 0; q < 4; q++) acc[mt][nt][q] = 0.f;

        const float* pA[2];
        const float* pA8[2];
#pragma unroll
        for (int mt = 0; mt < 2; mt++) {
            int r0 = rbase + mt * 16 + gid;
            if (r0 > N_NODES - 1) r0 = N_NODES - 1;
            pA[mt] = Xin + (size_t)r0 * OUTW + tig * 2;
            int r1 = rbase + mt * 16 + 8 + gid;
            if (r1 > N_NODES - 1) r1 = N_NODES - 1;
            pA8[mt] = Xin + (size_t)r1 * OUTW + tig * 2;
        }

#pragma unroll
        for (int ks = 0; ks < 8; ks++) {
            uint32_t ah[2][4], al[2][4];
#pragma unroll
            for (int mt = 0; mt < 2; mt++) {
                float2 v0 = __ldg((const float2*)(pA[mt]  + ks * 16));
                float2 v1 = __ldg((const float2*)(pA8[mt] + ks * 16));
                float2 v2 = __ldg((const float2*)(pA[mt]  + ks * 16 + 8));
                float2 v3 = __ldg((const float2*)(pA8[mt] + ks * 16 + 8));
                split2(v0.x, v0.y, ah[mt][0], al[mt][0]);
                split2(v1.x, v1.y, ah[mt][1], al[mt][1]);
                split2(v2.x, v2.y, ah[mt][2], al[mt][2]);
                split2(v3.x, v3.y, ah[mt][3], al[mt][3]);
            }
#pragma unroll
            for (int nt = 0; nt < 8; nt++) {
                uint4 b = sB[((wn * 8 + nt) * 8 + ks) * 32 + lane];
#pragma unroll
                for (int mt = 0; mt < 2; mt++) {
                    mma_bf16(acc[mt][nt], ah[mt], b.x, b.y);
                    mma_bf16(acc[mt][nt], ah[mt], b.z, b.w);
                    mma_bf16(acc[mt][nt], al[mt], b.x, b.y);
                }
            }
        }

#pragma unroll
        for (int mt = 0; mt < 2; mt++) {
#pragma unroll
            for (int h = 0; h < 2; h++) {
                int row = rbase + mt * 16 + h * 8 + gid;
                bool ok = row < N_NODES;
                int g = __ldg(batch + (ok ? row : N_NODES - 1));
                float* base = g_P12 + (size_t)row * 256;
#pragma unroll
                for (int np = 0; np < 4; np++) {
                    int nt0 = 2 * np, nt1 = 2 * np + 1;
                    float4 v = pair_combine(acc[mt][nt0][h * 2], acc[mt][nt0][h * 2 + 1],
                                            acc[mt][nt1][h * 2], acc[mt][nt1][h * 2 + 1],
                                            even);
                    int n = wn * 64 + (even ? nt0 : nt1) * 8 + (tig & 2) * 2;
                    if (ok) {
                        if (n < D) {
                            float4 uv = *(float4*)(sUW + g * D + n);
                            v.x += uv.x; v.y += uv.y; v.z += uv.z; v.w += uv.w;
                        }
                        *(float4*)(base + n) = v;
                    }
                }
            }
        }
    }
}

// ------------------------- edge kernel: mma.sync ----------------------------
// ea' = relu(ea@We3 + P1'[src] + P2[dst]); red.v4 to agg.
// A-path: LDG.128 + xor-1 exchange; tig-pair float4 epilogue.
__global__ void __launch_bounds__(256, 2) edge_mma_kernel(
    int step0, int store_ea, const float* __restrict__ ext_ea,
    const int* __restrict__ src, const int* __restrict__ dst,
    const float* __restrict__ We3) {
    extern __shared__ uint4 sBe[];   // [nt=16][ks=8][lane=32]
    int tid = threadIdx.x;

    for (int i = tid; i < 16 * 8 * 32; i += 256) {
        int lane = i & 31, ks = (i >> 5) & 7, nt = i >> 8;
        int gidw = lane >> 2, tigw = lane & 3;
        int n  = nt * 8 + gidw;
        int k0 = ks * 16 + tigw * 2;
        float w00 = __ldg(We3 + k0 * D + n);
        float w01 = __ldg(We3 + (k0 + 1) * D + n);
        float w10 = __ldg(We3 + (k0 + 8) * D + n);
        float w11 = __ldg(We3 + (k0 + 9) * D + n);
        uint32_t b0h, b0l, b1h, b1l;
        split2(w00, w01, b0h, b0l);
        split2(w10, w11, b1h, b1l);
        sBe[i] = make_uint4(b0h, b1h, b0l, b1l);
    }
    __syncthreads();

    int wid = tid >> 5, lane = tid & 31;
    int gid = lane >> 2, tig = lane & 3;
    int wm = wid & 3, wn = wid >> 2;
    bool even = ((tig & 1) == 0);
    int colo = ((tig & 1) << 3) + ((tig >> 1) << 2);   // (tig&1)*8 + (tig>>1)*4
    const float* ea_in = step0 ? ext_ea : (const float*)g_ea;

    for (int tile = blockIdx.x; tile < N_TILES; tile += gridDim.x) {
        const float* A = ea_in + (size_t)tile * (128 * 128);
        const float* base0 = A + (wm * 32 + 0 * 16 + gid) * 128 + colo;
        const float* base1 = A + (wm * 32 + 1 * 16 + gid) * 128 + colo;

        int sidx[2][2], didx[2][2];
#pragma unroll
        for (int mt = 0; mt < 2; mt++)
#pragma unroll
            for (int h = 0; h < 2; h++) {
                int r = tile * 128 + wm * 32 + mt * 16 + h * 8 + gid;
                sidx[mt][h] = __ldg(src + r);
                didx[mt][h] = __ldg(dst + r);
            }

        float acc[2][8][4];
#pragma unroll
        for (int mt = 0; mt < 2; mt++)
#pragma unroll
            for (int nt = 0; nt < 8; nt++)
#pragma unroll
                for (int q = 0; q < 4; q++) acc[mt][nt][q] = 0.f;

        // software-pipelined widened A loads: cur holds ks, nxt prefetches ks+1
        float4 cur[2][2], nxt[2][2];
#pragma unroll
        for (int mt = 0; mt < 2; mt++) {
            const float* b = mt ? base1 : base0;
            cur[mt][0] = __ldg((const float4*)b);             // row r
            cur[mt][1] = __ldg((const float4*)(b + 8 * 128)); // row r+8
        }
#pragma unroll
        for (int ks = 0; ks < 8; ks++) {
            if (ks < 7) {
#pragma unroll
                for (int mt = 0; mt < 2; mt++) {
                    const float* b = (mt ? base1 : base0) + (ks + 1) * 16;
                    nxt[mt][0] = __ldg((const float4*)b);
                    nxt[mt][1] = __ldg((const float4*)(b + 8 * 128));
                }
            }
            uint32_t ah[2][4], al[2][4];
#pragma unroll
            for (int mt = 0; mt < 2; mt++) {
                frag_from_f4(cur[mt][0], even, ah[mt][0], al[mt][0], ah[mt][2], al[mt][2]);
                frag_from_f4(cur[mt][1], even, ah[mt][1], al[mt][1], ah[mt][3], al[mt][3]);
            }
#pragma unroll
            for (int nt = 0; nt < 8; nt++) {
                uint4 b = sBe[((wn * 8 + nt) * 8 + ks) * 32 + lane];
#pragma unroll
                for (int mt = 0; mt < 2; mt++) {
                    mma_bf16(acc[mt][nt], ah[mt], b.x, b.y);
                    mma_bf16(acc[mt][nt], ah[mt], b.z, b.w);
                    mma_bf16(acc[mt][nt], al[mt], b.x, b.y);
                }
            }
#pragma unroll
            for (int mt = 0; mt < 2; mt++) {
                cur[mt][0] = nxt[mt][0];
                cur[mt][1] = nxt[mt][1];
            }
        }

        // tig-pair float4 epilogue
#pragma unroll
        for (int mt = 0; mt < 2; mt++) {
#pragma unroll
            for (int h = 0; h < 2; h++) {
                int r = tile * 128 + wm * 32 + mt * 16 + h * 8 + gid;
                int s = sidx[mt][h], d = didx[mt][h];
                const float* p1b = g_P12 + (size_t)s * 256;
                const float* p2b = g_P12 + (size_t)d * 256 + 128;
                float* eo = g_ea + (size_t)r * D;
                float* ao = g_agg + (size_t)d * D;
#pragma unroll
                for (int np = 0; np < 4; np++) {
                    int nt0 = 2 * np, nt1 = 2 * np + 1;
                    float4 v = pair_combine(acc[mt][nt0][h * 2], acc[mt][nt0][h * 2 + 1],
                                            acc[mt][nt1][h * 2], acc[mt][nt1][h * 2 + 1],
                                            even);
                    int c = wn * 64 + (even ? nt0 : nt1) * 8 + (tig & 2) * 2;
                    float4 p1 = __ldg((const float4*)(p1b + c));
                    float4 p2 = __ldg((const float4*)(p2b + c));
                    float4 rr;
                    rr.x = fmaxf(v.x + p1.x + p2.x, 0.f);
                    rr.y = fmaxf(v.y + p1.y + p2.y, 0.f);
                    rr.z = fmaxf(v.z + p1.z + p2.z, 0.f);
                    rr.w = fmaxf(v.w + p1.w + p2.w, 0.f);
                    if (store_ea) *(float4*)(eo + c) = rr;
                    red_add4(ao + c, rr);
                }
            }
        }
    }
}

// --------------------------- prep2 (uWn3b only) -----------------------------
__global__ void prep2_kernel(const float* __restrict__ W_node,
                             const float* __restrict__ b_node) {
    int g = blockIdx.x, j = threadIdx.x;
    __shared__ float su[D];
    su[j] = g_u[g * D + j];
    __syncthreads();
    const float* W3 = W_node + 2 * D * D;
    float acc = b_node[j];
#pragma unroll 8
    for (int k = 0; k < D; k++) acc = fmaf(su[k], W3[k * D + j], acc);
    g_uWn3b[g * D + j] = acc;
}

// ------------------------- node kernel (mma.sync, 512 thr) ------------------
// x' = relu([x, agg/deg] @ Wn12 + uWn3b[batch]); red.v4 per-graph sums;
// zeroes agg for next step in its epilogue (barrier-protected).
__global__ void __launch_bounds__(512, 1) node_mma_kernel(
    const float* __restrict__ Xin, float* __restrict__ Xout,
    const int* __restrict__ batch, const float* __restrict__ W_node) {
    extern __shared__ char smemraw[];
    uint4* sB = (uint4*)smemraw;                  // [nt16][ks16][lane32] 128 KB
    float* sU = (float*)(smemraw + 131072);       // 8 KB
    int tid = threadIdx.x;

    for (int i = tid; i < 16 * 16 * 32; i += 512) {
        int lane = i & 31, ks = (i >> 5) & 15, nt = i >> 9;
        int gidw = lane >> 2, tigw = lane & 3;
        int n  = nt * 8 + gidw;
        int k0 = ks * 16 + tigw * 2;
        float w00 = __ldg(W_node + k0 * D + n);
        float w01 = __ldg(W_node + (k0 + 1) * D + n);
        float w10 = __ldg(W_node + (k0 + 8) * D + n);
        float w11 = __ldg(W_node + (k0 + 9) * D + n);
        uint32_t b0h, b0l, b1h, b1l;
        split2(w00, w01, b0h, b0l);
        split2(w10, w11, b1h, b1l);
        sB[i] = make_uint4(b0h, b1h, b0l, b1l);
    }
    for (int i = tid; i < N_GRAPHS * D; i += 512) sU[i] = g_uWn3b[i];
    __syncthreads();

    int wid = tid >> 5, lane = tid & 31;
    int gid = lane >> 2, tig = lane & 3;
    int wm = wid & 3, wn = wid >> 2;
    bool even = ((tig & 1) == 0);

    for (int tile = blockIdx.x; tile < N_RTILES; tile += gridDim.x) {
        int rbase = tile * 128 + wm * 32;
        int r0c[2], r1c[2];
        float inv0[2], inv1[2];
#pragma unroll
        for (int mt = 0; mt < 2; mt++) {
            int r0 = rbase + mt * 16 + gid;      if (r0 > N_NODES - 1) r0 = N_NODES - 1;
            int r1 = rbase + mt * 16 + 8 + gid;  if (r1 > N_NODES - 1) r1 = N_NODES - 1;
            r0c[mt] = r0; r1c[mt] = r1;
            inv0[mt] = __ldg(&g_invN[r0]);
            inv1[mt] = __ldg(&g_invN[r1]);
        }

        float acc[2][4][4];
#pragma unroll
        for (int mt = 0; mt < 2; mt++)
#pragma unroll
            for (int nt = 0; nt < 4; nt++)
#pragma unroll
                for (int q = 0; q < 4; q++) acc[mt][nt][q] = 0.f;

#pragma unroll
        for (int ks = 0; ks < 16; ks++) {
            uint32_t ah[2][4], al[2][4];
#pragma unroll
            for (int mt = 0; mt < 2; mt++) {
                float2 v0, v1, v2, v3;
                if (ks < 8) {
                    const float* p0 = Xin + (size_t)r0c[mt] * OUTW + ks * 16 + tig * 2;
                    const float* p1 = Xin + (size_t)r1c[mt] * OUTW + ks * 16 + tig * 2;
                    v0 = __ldg((const float2*)p0);
                    v1 = __ldg((const float2*)p1);
                    v2 = __ldg((const float2*)(p0 + 8));
                    v3 = __ldg((const float2*)(p1 + 8));
                } else {
                    const float* p0 = g_agg + (size_t)r0c[mt] * D + (ks - 8) * 16 + tig * 2;
                    const float* p1 = g_agg + (size_t)r1c[mt] * D + (ks - 8) * 16 + tig * 2;
                    v0 = __ldg((const float2*)p0);
                    v1 = __ldg((const float2*)p1);
                    v2 = __ldg((const float2*)(p0 + 8));
                    v3 = __ldg((const float2*)(p1 + 8));
                    v0.x *= inv0[mt]; v0.y *= inv0[mt];
                    v1.x *= inv1[mt]; v1.y *= inv1[mt];
                    v2.x *= inv0[mt]; v2.y *= inv0[mt];
                    v3.x *= inv1[mt]; v3.y *= inv1[mt];
                }
                split2(v0.x, v0.y, ah[mt][0], al[mt][0]);
                split2(v1.x, v1.y, ah[mt][1], al[mt][1]);
                split2(v2.x, v2.y, ah[mt][2], al[mt][2]);
                split2(v3.x, v3.y, ah[mt][3], al[mt][3]);
            }
#pragma unroll
            for (int nt = 0; nt < 4; nt++) {
                uint4 b = sB[((wn * 4 + nt) * 16 + ks) * 32 + lane];
#pragma unroll
                for (int mt = 0; mt < 2; mt++) {
                    mma_bf16(acc[mt][nt], ah[mt], b.x, b.y);
                    mma_bf16(acc[mt][nt], ah[mt], b.z, b.w);
                    mma_bf16(acc[mt][nt], al[mt], b.x, b.y);
                }
            }
        }

        // all agg reads of this tile done before epilogue zeroes agg rows
        __syncthreads();

        // tig-pair float4 epilogue: Xout rows + red.v4 + agg zeroing
#pragma unroll
        for (int mt = 0; mt < 2; mt++) {
#pragma unroll
            for (int h = 0; h < 2; h++) {
                int row = rbase + mt * 16 + h * 8 + gid;
                bool ok = row < N_NODES;
                int g = __ldg(batch + (ok ? row : N_NODES - 1));
                float* xo = Xout + (size_t)row * OUTW;
                float* ag = g_agg + (size_t)row * D;
#pragma unroll
                for (int np = 0; np < 2; np++) {
                    int nt0 = 2 * np, nt1 = 2 * np + 1;
                    float4 v = pair_combine(acc[mt][nt0][h * 2], acc[mt][nt0][h * 2 + 1],
                                            acc[mt][nt1][h * 2], acc[mt][nt1][h * 2 + 1],
                                            even);
                    int c = wn * 32 + (even ? nt0 : nt1) * 8 + (tig & 2) * 2;
                    if (ok) {
                        float4 uv = *(float4*)(sU + g * D + c);
                        float4 rr;
                        rr.x = fmaxf(v.x + uv.x, 0.f);
                        rr.y = fmaxf(v.y + uv.y, 0.f);
                        rr.z = fmaxf(v.z + uv.z, 0.f);
                        rr.w = fmaxf(v.w + uv.w, 0.f);
                        *(float4*)(xo + c) = rr;
                        red_add4(g_gsum + g * D + c, rr);
                        *(float4*)(ag + c) = make_float4(0.f, 0.f, 0.f, 0.f);
                    }
                }
            }
        }
    }
}

// ------------------------------ global kernel ------------------------------
__global__ void global_kernel(const float* __restrict__ W_glob,
                              const float* __restrict__ b_glob,
                              float* __restrict__ out_g) {
    int g = blockIdx.x;
    int j = threadIdx.x;
    __shared__ float su[D], sm[D];
    su[j] = g_u[g * D + j];
    sm[j] = g_gsum[g * D + j] * g_invG[g];
    g_gsum[g * D + j] = 0.f;      // ready for next step / next replay
    __syncthreads();
    float acc = b_glob[j];
#pragma unroll 4
    for (int k = 0; k < D; k++) acc = fmaf(su[k], W_glob[k * D + j], acc);
#pragma unroll 4
    for (int k = 0; k < D; k++) acc = fmaf(sm[k], W_glob[(D + k) * D + j], acc);
    float r = fmaxf(acc, 0.f);
    out_g[(size_t)g * OUTW + j] = r;
    g_u[g * D + j] = r;
}

// --------------------------------- launch ----------------------------------
extern "C" void kernel_launch(void* const* d_in, const int* in_sizes, int n_in,
                              void* d_out, int out_size) {
    const float* x      = (const float*)d_in[0];
    const int*   ei     = (const int*)d_in[1];
    const float* ea     = (const float*)d_in[2];
    const float* u      = (const float*)d_in[3];
    const int*   batch  = (const int*)d_in[4];
    const float* W_edge = (const float*)d_in[5];
    const float* b_edge = (const float*)d_in[6];
    const float* W_node = (const float*)d_in[7];
    const float* b_node = (const float*)d_in[8];
    const float* W_glob = (const float*)d_in[9];
    const float* b_glob = (const float*)d_in[10];

    const int* src = ei;
    const int* dstp = ei + N_EDGES;

    float* out   = (float*)d_out;
    float* out_x = out;                            // 50000 x 512
    float* out_g = out + (size_t)N_NODES * OUTW;   // 16 x 512

    const int MV_SMEM   = 131072 + 8192 + 8192;    // 147456
    const int EDGE_SMEM = 16 * 8 * 32 * 16;        // 64 KB
    const int NODE_SMEM = 131072 + 8192;           // 139264

    cudaFuncSetAttribute(matvec_mma_kernel, cudaFuncAttributeMaxDynamicSharedMemorySize, MV_SMEM);
    cudaFuncSetAttribute(edge_mma_kernel,   cudaFuncAttributeMaxDynamicSharedMemorySize, EDGE_SMEM);
    cudaFuncSetAttribute(node_mma_kernel,   cudaFuncAttributeMaxDynamicSharedMemorySize, NODE_SMEM);

    // launch order: index 3 (ncu capture point) = edge_mma_kernel
    init_kernel<<<2048, 256>>>(x, u, out_x, out_g);                          // 0
    matvec_mma_kernel<<<148, 512, MV_SMEM>>>(out_x, W_edge, b_edge, batch);  // 1 (t=0)
    hist_kernel<<<1024, 256>>>(dstp, batch);                                 // 2
    edge_mma_kernel<<<296, 256, EDGE_SMEM>>>(1, 1, ea, src, dstp,            // 3 PROFILED
                                             W_edge + 2 * D * D);
    finalize_counts_kernel<<<256, 256>>>();                                  // 4

    for (int t = 0; t < 3; t++) {
        const float* Xt = out_x + t * D;
        float*       Xn = out_x + (t + 1) * D;

        prep2_kernel<<<16, 128>>>(W_node, b_node);
        node_mma_kernel<<<148, 512, NODE_SMEM>>>(Xt, Xn, batch, W_node);
        global_kernel<<<16, 128>>>(W_glob, b_glob, out_g + (t + 1) * D);

        if (t < 2) {
            matvec_mma_kernel<<<148, 512, MV_SMEM>>>(Xn, W_edge, b_edge, batch);
            edge_mma_kernel<<<296, 256, EDGE_SMEM>>>(0, (t + 1) < 2 ? 1 : 0, ea,
                                                     src, dstp, W_edge + 2 * D * D);
        }
    }
}